// round 11
// baseline (speedup 1.0000x reference)
#include <cuda_runtime.h>
#include <cuda_bf16.h>
#include <math.h>

#define Bn 256
#define Sn 128
#define Dn 768
#define K2 1536
#define MASK_ID 103
#define KSPLIT 16
#define KCH (K2 / KSPLIT)   // 96
#define NIT (KCH / 32)      // 3

// Scratch (__device__ globals; no allocs allowed)
__device__ __nv_bfloat16 g_featsH[Bn * K2];     // feats bf16 hi
__device__ __nv_bfloat16 g_featsL[Bn * K2];     // feats bf16 lo
__device__ __nv_bfloat16 g_WH[Dn * K2];         // dense_w bf16 hi
__device__ __nv_bfloat16 g_WL[Dn * K2];         // dense_w bf16 lo
__device__ float g_part[KSPLIT][Bn * Dn];       // split-K partials
__device__ float g_h[Bn * Dn];                  // tanh dense output
__device__ int   g_ctr[4][12];                  // tile arrival counters (self-reset)

static __device__ const int c_ids[21] = {
    2307, 2204, 3835, 2157, 6581, 2986, 5151, 3893,
    7929, 24791, 8699, 4257, 16021, 6623,
    6659, 2919, 11771, 3532, 11325, 4997, 13135
};

__device__ __forceinline__ void split_store(
    __nv_bfloat16* ph, __nv_bfloat16* pl, float v)
{
    const __nv_bfloat16 h = __float2bfloat16(v);
    *ph = h;
    *pl = __float2bfloat16(v - __bfloat162float(h));
}

// ---------------------------------------------------------------------------
// kW: split dense_w into bf16 hi/lo
// ---------------------------------------------------------------------------
__global__ __launch_bounds__(256) void kW(const float* __restrict__ Wd)
{
    const int i = (blockIdx.x * 256 + threadIdx.x) * 4;
    const float4 v = *(const float4*)&Wd[i];
    __nv_bfloat16 h[4], l[4];
    h[0] = __float2bfloat16(v.x); l[0] = __float2bfloat16(v.x - __bfloat162float(h[0]));
    h[1] = __float2bfloat16(v.y); l[1] = __float2bfloat16(v.y - __bfloat162float(h[1]));
    h[2] = __float2bfloat16(v.z); l[2] = __float2bfloat16(v.z - __bfloat162float(h[2]));
    h[3] = __float2bfloat16(v.w); l[3] = __float2bfloat16(v.w - __bfloat162float(h[3]));
    *(uint2*)&g_WH[i] = *(uint2*)h;
    *(uint2*)&g_WL[i] = *(uint2*)l;
}

// ---------------------------------------------------------------------------
// kA: FULLY FUSED per-batch attention stage. One block per batch, 576 thr.
// ---------------------------------------------------------------------------
__global__ __launch_bounds__(576) void kA(
    const float* __restrict__ bert,
    const int*   __restrict__ ids,
    const int*   __restrict__ length,
    const float* __restrict__ senti_w,
    const float* __restrict__ senti_b,
    float*       __restrict__ out)
{
    const int b = blockIdx.x;
    const int t = threadIdx.x;
    const int warp = t >> 5, lane = t & 31;
    const int len = length[b];

    __shared__ float ml[Dn];
    __shared__ float sc[112];
    __shared__ float pool[3][Dn];
    __shared__ float red[18];
    __shared__ int   mp_s;

    if (t < Sn && ids[b * Sn + t] == MASK_ID) mp_s = t;
    __syncthreads();
    const int mp = mp_s;
    const float* Xb = bert + (size_t)b * Sn * Dn;

    for (int d = t; d < Dn; d += 576) {
        const float v = Xb[(size_t)mp * Dn + d];
        ml[d] = v;
        split_store(&g_featsH[(size_t)b * K2 + Dn + d],
                    &g_featsL[(size_t)b * K2 + Dn + d], v);
    }
    __syncthreads();

    // category head (pooler = row 0), warps 16/17
    if (warp >= 16) {
        const int c = warp - 16;
        float s = 0.f;
        for (int d = lane * 4; d < Dn; d += 128) {
            const float4 x = *(const float4*)&Xb[d];
            const float4 w = *(const float4*)&senti_w[c * Dn + d];
            s += x.x * w.x + x.y * w.y + x.z * w.z + x.w * w.w;
        }
        #pragma unroll
        for (int o = 16; o > 0; o >>= 1) s += __shfl_xor_sync(0xffffffffu, s, o);
        if (lane == 0) out[b * 2 + c] = s + senti_b[c];
    }

    for (int s = warp; s < len; s += 18) {
        const float* row = Xb + (size_t)(s + 3) * Dn;
        float acc = 0.f;
        #pragma unroll
        for (int j = 0; j < 6; ++j) {
            const int d = j * 128 + lane * 4;
            const float4 x = *(const float4*)&row[d];
            const float4 m = *(const float4*)&ml[d];
            acc += x.x * m.x + x.y * m.y + x.z * m.z + x.w * m.w;
        }
        #pragma unroll
        for (int o = 16; o > 0; o >>= 1) acc += __shfl_xor_sync(0xffffffffu, acc, o);
        if (lane == 0) sc[s] = acc;
    }
    __syncthreads();

    float v = (t < len) ? sc[t] : -INFINITY;
    float m = v;
    #pragma unroll
    for (int o = 16; o > 0; o >>= 1) m = fmaxf(m, __shfl_xor_sync(0xffffffffu, m, o));
    if (lane == 0) red[warp] = m;
    __syncthreads();
    m = red[0];
    #pragma unroll
    for (int i = 1; i < 18; ++i) m = fmaxf(m, red[i]);
    __syncthreads();

    float e = (t < len) ? __expf(v - m) : 0.f;
    float su = e;
    #pragma unroll
    for (int o = 16; o > 0; o >>= 1) su += __shfl_xor_sync(0xffffffffu, su, o);
    if (lane == 0) red[warp] = su;
    __syncthreads();
    su = 0.f;
    #pragma unroll
    for (int i = 0; i < 18; ++i) su += red[i];
    const float inv = 1.f / su;
    __syncthreads();
    if (t < len) sc[t] = e * inv;
    __syncthreads();

    const int g  = t / 192;
    const int tg = t - g * 192;
    const float* Xp = Xb + (size_t)3 * Dn + tg * 4;

    float4 A0 = {0,0,0,0}, A1 = {0,0,0,0};
    int s = g;
    for (; s + 3 < len; s += 6) {
        const float w0 = sc[s], w1 = sc[s + 3];
        const float4 x0 = *(const float4*)&Xp[(size_t)s * Dn];
        const float4 x1 = *(const float4*)&Xp[(size_t)(s + 3) * Dn];
        A0.x += w0 * x0.x; A0.y += w0 * x0.y; A0.z += w0 * x0.z; A0.w += w0 * x0.w;
        A1.x += w1 * x1.x; A1.y += w1 * x1.y; A1.z += w1 * x1.z; A1.w += w1 * x1.w;
    }
    for (; s < len; s += 3) {
        const float w0 = sc[s];
        const float4 x0 = *(const float4*)&Xp[(size_t)s * Dn];
        A0.x += w0 * x0.x; A0.y += w0 * x0.y; A0.z += w0 * x0.z; A0.w += w0 * x0.w;
    }
    float4 r;
    r.x = A0.x + A1.x; r.y = A0.y + A1.y; r.z = A0.z + A1.z; r.w = A0.w + A1.w;
    *(float4*)&pool[g][tg * 4] = r;
    __syncthreads();

    if (t < 192) {
        const int d = t * 4;
        const float4 p0 = *(const float4*)&pool[0][d];
        const float4 p1 = *(const float4*)&pool[1][d];
        const float4 p2 = *(const float4*)&pool[2][d];
        float sv[4];
        sv[0] = (p0.x + p1.x) + p2.x;
        sv[1] = (p0.y + p1.y) + p2.y;
        sv[2] = (p0.z + p1.z) + p2.z;
        sv[3] = (p0.w + p1.w) + p2.w;
        __nv_bfloat16 h[4], l[4];
        #pragma unroll
        for (int i = 0; i < 4; ++i) {
            h[i] = __float2bfloat16(sv[i]);
            l[i] = __float2bfloat16(sv[i] - __bfloat162float(h[i]));
        }
        *(uint2*)&g_featsH[(size_t)b * K2 + d] = *(uint2*)h;
        *(uint2*)&g_featsL[(size_t)b * K2 + d] = *(uint2*)l;
    }
}

// ---------------------------------------------------------------------------
// kB: bf16 tensor-core GEMM (split-bf16 emulated fp32), cp.async 2-stage,
// KSPLIT=16 + LAST-BLOCK-REDUCES tail: the 16th z-block per (bm,bn) tile
// sums the (L2-hot) partials + bias + tanh -> g_h. Deterministic.
// ---------------------------------------------------------------------------
#define LDK 40   // 80B rows, conflict-free ldmatrix

__device__ __forceinline__ void mma_bf16(
    float* c, const unsigned* a, const unsigned* b)
{
    asm volatile(
        "mma.sync.aligned.m16n8k16.row.col.f32.bf16.bf16.f32 "
        "{%0,%1,%2,%3}, {%4,%5,%6,%7}, {%8,%9}, {%0,%1,%2,%3};"
        : "+f"(c[0]), "+f"(c[1]), "+f"(c[2]), "+f"(c[3])
        : "r"(a[0]), "r"(a[1]), "r"(a[2]), "r"(a[3]), "r"(b[0]), "r"(b[1]));
}

__device__ __forceinline__ void ldsm4(unsigned* r, unsigned addr)
{
    asm volatile("ldmatrix.sync.aligned.m8n8.x4.shared.b16 {%0,%1,%2,%3}, [%4];"
                 : "=r"(r[0]), "=r"(r[1]), "=r"(r[2]), "=r"(r[3]) : "r"(addr));
}

__device__ __forceinline__ void cp16(void* dst, const void* src)
{
    const unsigned d = (unsigned)__cvta_generic_to_shared(dst);
    asm volatile("cp.async.ca.shared.global [%0], [%1], 16;" :: "r"(d), "l"(src));
}

__global__ __launch_bounds__(128) void kB(const float* __restrict__ bd)
{
    __shared__ __nv_bfloat16 smem[2][4][64 * LDK];
    __shared__ int last_s;

    const int t = threadIdx.x;
    const int warp = t >> 5, lane = t & 31;
    const int bn = blockIdx.x * 64;
    const int bm = blockIdx.y * 64;
    const int kbase = blockIdx.z * KCH;
    const int wm = warp & 1, wn = warp >> 1;

    float acc[2][4][4] = {};

    const int row = t >> 2;
    const int cq  = (t & 3) * 8;

    #define ISSUE(it, stg) do {                                                   \
        const int kg = kbase + (it) * 32;                                          \
        _Pragma("unroll")                                                          \
        for (int i = 0; i < 2; ++i) {                                              \
            const int r = row + i * 32;                                            \
            cp16(&smem[stg][0][r * LDK + cq], &g_featsH[(size_t)(bm + r) * K2 + kg + cq]); \
            cp16(&smem[stg][1][r * LDK + cq], &g_featsL[(size_t)(bm + r) * K2 + kg + cq]); \
            cp16(&smem[stg][2][r * LDK + cq], &g_WH[(size_t)(bn + r) * K2 + kg + cq]);     \
            cp16(&smem[stg][3][r * LDK + cq], &g_WL[(size_t)(bn + r) * K2 + kg + cq]);     \
        }                                                                          \
        asm volatile("cp.async.commit_group;");                                    \
    } while (0)

    ISSUE(0, 0);

    for (int it = 0; it < NIT; ++it) {
        const int stg = it & 1;
        if (it + 1 < NIT) {
            ISSUE(it + 1, stg ^ 1);
            asm volatile("cp.async.wait_group 1;");
        } else {
            asm volatile("cp.async.wait_group 0;");
        }
        __syncthreads();

        const unsigned ah_b = (unsigned)__cvta_generic_to_shared(smem[stg][0]);
        const unsigned al_b = (unsigned)__cvta_generic_to_shared(smem[stg][1]);
        const unsigned bh_b = (unsigned)__cvta_generic_to_shared(smem[stg][2]);
        const unsigned bl_b = (unsigned)__cvta_generic_to_shared(smem[stg][3]);

        #pragma unroll
        for (int kk = 0; kk < 32; kk += 16) {
            unsigned Ah[2][4], Al[2][4];
            #pragma unroll
            for (int tm = 0; tm < 2; ++tm) {
                const unsigned off =
                    (unsigned)(((wm * 32 + tm * 16 + (lane & 15)) * LDK
                               + kk + (lane >> 4) * 8) * 2);
                ldsm4(Ah[tm], ah_b + off);
                ldsm4(Al[tm], al_b + off);
            }
            unsigned Bh[4][2], Bl[4][2];
            #pragma unroll
            for (int bj = 0; bj < 2; ++bj) {
                const int quad = lane >> 3, l8 = lane & 7;
                const int n = wn * 32 + bj * 16 + (quad >> 1) * 8 + l8;
                const int k = kk + (quad & 1) * 8;
                const unsigned off = (unsigned)((n * LDK + k) * 2);
                unsigned r4[4];
                ldsm4(r4, bh_b + off);
                Bh[bj * 2][0] = r4[0]; Bh[bj * 2][1] = r4[1];
                Bh[bj * 2 + 1][0] = r4[2]; Bh[bj * 2 + 1][1] = r4[3];
                ldsm4(r4, bl_b + off);
                Bl[bj * 2][0] = r4[0]; Bl[bj * 2][1] = r4[1];
                Bl[bj * 2 + 1][0] = r4[2]; Bl[bj * 2 + 1][1] = r4[3];
            }
            #pragma unroll
            for (int tm = 0; tm < 2; ++tm)
                #pragma unroll
                for (int tn = 0; tn < 4; ++tn) {
                    mma_bf16(acc[tm][tn], Ah[tm], Bh[tn]);
                    mma_bf16(acc[tm][tn], Ah[tm], Bl[tn]);
                    mma_bf16(acc[tm][tn], Al[tm], Bh[tn]);
                }
        }
        __syncthreads();
    }

    float* P = g_part[blockIdx.z];
    const int r0 = bm + wm * 32 + (lane >> 2);
    const int c0 = bn + wn * 32 + (lane & 3) * 2;
    #pragma unroll
    for (int tm = 0; tm < 2; ++tm)
        #pragma unroll
        for (int tn = 0; tn < 4; ++tn) {
            const int r = r0 + tm * 16;
            const int c = c0 + tn * 8;
            *(float2*)&P[(size_t)r * Dn + c]       = make_float2(acc[tm][tn][0], acc[tm][tn][1]);
            *(float2*)&P[(size_t)(r + 8) * Dn + c] = make_float2(acc[tm][tn][2], acc[tm][tn][3]);
        }

    // ---- last-block-reduces tail ----
    __threadfence();
    __syncthreads();
    if (t == 0)
        last_s = (atomicAdd(&g_ctr[blockIdx.y][blockIdx.x], 1) == KSPLIT - 1);
    __syncthreads();
    if (!last_s) return;

    #pragma unroll
    for (int i = 0; i < 8; ++i) {
        const int pos = t + i * 128;          // float4 index within 64x64 tile
        const int r   = pos >> 4;             // row 0..63
        const int c   = (pos & 15) * 4;       // col 0..60
        const size_t gi = (size_t)(bm + r) * Dn + bn + c;
        float4 s = *(const float4*)&bd[bn + c];
        #pragma unroll
        for (int k = 0; k < KSPLIT; ++k) {
            const float4 p = *(const float4*)&g_part[k][gi];
            s.x += p.x; s.y += p.y; s.z += p.z; s.w += p.w;
        }
        float4 h4;
        h4.x = tanhf(s.x); h4.y = tanhf(s.y);
        h4.z = tanhf(s.z); h4.w = tanhf(s.w);
        *(float4*)&g_h[gi] = h4;
    }

    // reset counter for next graph replay (after all reads of partials)
    __syncthreads();
    if (t == 0) g_ctr[blockIdx.y][blockIdx.x] = 0;
}

// ---------------------------------------------------------------------------
// kC: 21 decoder rows + label-group mixes (reads L2-hot g_h)
// ---------------------------------------------------------------------------
__global__ __launch_bounds__(256) void kC(
    const float* __restrict__ dec_w,
    const float* __restrict__ dec_b,
    const float* __restrict__ w0,
    const float* __restrict__ w1,
    const float* __restrict__ w2,
    float*       __restrict__ out)
{
    const int b = blockIdx.x;
    const int t = threadIdx.x;
    const int warp = t >> 5, lane = t & 31;

    __shared__ float hs[Dn];
    __shared__ float probs[21];

    if (t < 192) *(float4*)&hs[t * 4] = *(const float4*)&g_h[(size_t)b * Dn + t * 4];
    __syncthreads();

    for (int j = warp; j < 21; j += 8) {
        const int v = c_ids[j];
        const float* rw = dec_w + (size_t)v * Dn;
        float s = 0.f;
        for (int d = lane * 4; d < Dn; d += 128) {
            const float4 h4 = *(const float4*)&hs[d];
            const float4 r4 = *(const float4*)&rw[d];
            s += h4.x * r4.x + h4.y * r4.y + h4.z * r4.z + h4.w * r4.w;
        }
        #pragma unroll
        for (int o = 16; o > 0; o >>= 1) s += __shfl_xor_sync(0xffffffffu, s, o);
        if (lane == 0) probs[j] = tanhf(s + dec_b[v]);
    }
    __syncthreads();

    if (t < 6) {
        const int o = t / 3, g = t % 3;
        const float* w = (g == 0) ? w0 : (g == 1) ? w1 : w2;
        const int off = (g == 0) ? 0 : (g == 1) ? 8 : 14;
        const int n   = (g == 0) ? 8 : (g == 1) ? 6 : 7;
        float s = 0.f;
        for (int j = 0; j < n; ++j) s += probs[off + j] * w[o * n + j];
        out[2 * Bn + b * 6 + o * 3 + g] = s;
    }
}

// ---------------------------------------------------------------------------
extern "C" void kernel_launch(void* const* d_in, const int* in_sizes, int n_in,
                              void* d_out, int out_size)
{
    const float* bert    = (const float*)d_in[0];
    const int*   ids     = (const int*)  d_in[1];
    const int*   length  = (const int*)  d_in[2];
    const float* senti_w = (const float*)d_in[3];
    const float* senti_b = (const float*)d_in[4];
    const float* dense_w = (const float*)d_in[5];
    const float* dense_b = (const float*)d_in[6];
    const float* dec_w   = (const float*)d_in[7];
    const float* dec_b   = (const float*)d_in[8];
    const float* w0      = (const float*)d_in[9];
    const float* w1      = (const float*)d_in[10];
    const float* w2      = (const float*)d_in[11];
    float* out = (float*)d_out;

    kW<<<(Dn * K2) / 1024, 256>>>(dense_w);
    kA<<<Bn, 576>>>(bert, ids, length, senti_w, senti_b, out);
    kB<<<dim3(Dn / 64, Bn / 64, KSPLIT), 128>>>(dense_b);
    kC<<<Bn, 256>>>(dec_w, dec_b, w0, w1, w2, out);
}

// round 12
// speedup vs baseline: 1.2715x; 1.2715x over previous
#include <cuda_runtime.h>
#include <cuda_bf16.h>
#include <math.h>

#define Bn 256
#define Sn 128
#define Dn 768
#define K2 1536
#define MASK_ID 103
#define KSPLIT 16
#define KCH (K2 / KSPLIT)   // 96
#define NIT (KCH / 32)      // 3

// Scratch (__device__ globals; no allocs allowed)
__device__ __nv_bfloat16 g_featsH[Bn * K2];     // feats bf16 hi
__device__ __nv_bfloat16 g_featsL[Bn * K2];     // feats bf16 lo
__device__ __nv_bfloat16 g_WH[Dn * K2];         // dense_w bf16 hi
__device__ __nv_bfloat16 g_WL[Dn * K2];         // dense_w bf16 lo
__device__ float g_part[KSPLIT][Bn * Dn];       // split-K partials
__device__ float g_h[Bn * Dn];                  // tanh dense output

static __device__ const int c_ids[21] = {
    2307, 2204, 3835, 2157, 6581, 2986, 5151, 3893,
    7929, 24791, 8699, 4257, 16021, 6623,
    6659, 2919, 11771, 3532, 11325, 4997, 13135
};

__device__ __forceinline__ void split_store(
    __nv_bfloat16* ph, __nv_bfloat16* pl, float v)
{
    const __nv_bfloat16 h = __float2bfloat16(v);
    *ph = h;
    *pl = __float2bfloat16(v - __bfloat162float(h));
}

// ---------------------------------------------------------------------------
// kW: split dense_w into bf16 hi/lo
// ---------------------------------------------------------------------------
__global__ __launch_bounds__(256) void kW(const float* __restrict__ Wd)
{
    const int i = (blockIdx.x * 256 + threadIdx.x) * 4;
    const float4 v = *(const float4*)&Wd[i];
    __nv_bfloat16 h[4], l[4];
    h[0] = __float2bfloat16(v.x); l[0] = __float2bfloat16(v.x - __bfloat162float(h[0]));
    h[1] = __float2bfloat16(v.y); l[1] = __float2bfloat16(v.y - __bfloat162float(h[1]));
    h[2] = __float2bfloat16(v.z); l[2] = __float2bfloat16(v.z - __bfloat162float(h[2]));
    h[3] = __float2bfloat16(v.w); l[3] = __float2bfloat16(v.w - __bfloat162float(h[3]));
    *(uint2*)&g_WH[i] = *(uint2*)h;
    *(uint2*)&g_WL[i] = *(uint2*)l;
}

// ---------------------------------------------------------------------------
// kA: FULLY FUSED per-batch attention stage. One block per batch, 576 thr.
// ---------------------------------------------------------------------------
__global__ __launch_bounds__(576) void kA(
    const float* __restrict__ bert,
    const int*   __restrict__ ids,
    const int*   __restrict__ length,
    const float* __restrict__ senti_w,
    const float* __restrict__ senti_b,
    float*       __restrict__ out)
{
    const int b = blockIdx.x;
    const int t = threadIdx.x;
    const int warp = t >> 5, lane = t & 31;
    const int len = length[b];

    __shared__ float ml[Dn];
    __shared__ float sc[112];
    __shared__ float pool[3][Dn];
    __shared__ float red[18];
    __shared__ int   mp_s;

    if (t < Sn && ids[b * Sn + t] == MASK_ID) mp_s = t;
    __syncthreads();
    const int mp = mp_s;
    const float* Xb = bert + (size_t)b * Sn * Dn;

    for (int d = t; d < Dn; d += 576) {
        const float v = Xb[(size_t)mp * Dn + d];
        ml[d] = v;
        split_store(&g_featsH[(size_t)b * K2 + Dn + d],
                    &g_featsL[(size_t)b * K2 + Dn + d], v);
    }
    __syncthreads();

    // category head (pooler = row 0), warps 16/17
    if (warp >= 16) {
        const int c = warp - 16;
        float s = 0.f;
        for (int d = lane * 4; d < Dn; d += 128) {
            const float4 x = *(const float4*)&Xb[d];
            const float4 w = *(const float4*)&senti_w[c * Dn + d];
            s += x.x * w.x + x.y * w.y + x.z * w.z + x.w * w.w;
        }
        #pragma unroll
        for (int o = 16; o > 0; o >>= 1) s += __shfl_xor_sync(0xffffffffu, s, o);
        if (lane == 0) out[b * 2 + c] = s + senti_b[c];
    }

    for (int s = warp; s < len; s += 18) {
        const float* row = Xb + (size_t)(s + 3) * Dn;
        float acc = 0.f;
        #pragma unroll
        for (int j = 0; j < 6; ++j) {
            const int d = j * 128 + lane * 4;
            const float4 x = *(const float4*)&row[d];
            const float4 m = *(const float4*)&ml[d];
            acc += x.x * m.x + x.y * m.y + x.z * m.z + x.w * m.w;
        }
        #pragma unroll
        for (int o = 16; o > 0; o >>= 1) acc += __shfl_xor_sync(0xffffffffu, acc, o);
        if (lane == 0) sc[s] = acc;
    }
    __syncthreads();

    float v = (t < len) ? sc[t] : -INFINITY;
    float m = v;
    #pragma unroll
    for (int o = 16; o > 0; o >>= 1) m = fmaxf(m, __shfl_xor_sync(0xffffffffu, m, o));
    if (lane == 0) red[warp] = m;
    __syncthreads();
    m = red[0];
    #pragma unroll
    for (int i = 1; i < 18; ++i) m = fmaxf(m, red[i]);
    __syncthreads();

    float e = (t < len) ? __expf(v - m) : 0.f;
    float su = e;
    #pragma unroll
    for (int o = 16; o > 0; o >>= 1) su += __shfl_xor_sync(0xffffffffu, su, o);
    if (lane == 0) red[warp] = su;
    __syncthreads();
    su = 0.f;
    #pragma unroll
    for (int i = 0; i < 18; ++i) su += red[i];
    const float inv = 1.f / su;
    __syncthreads();
    if (t < len) sc[t] = e * inv;
    __syncthreads();

    const int g  = t / 192;
    const int tg = t - g * 192;
    const float* Xp = Xb + (size_t)3 * Dn + tg * 4;

    float4 A0 = {0,0,0,0}, A1 = {0,0,0,0};
    int s = g;
    for (; s + 3 < len; s += 6) {
        const float w0 = sc[s], w1 = sc[s + 3];
        const float4 x0 = *(const float4*)&Xp[(size_t)s * Dn];
        const float4 x1 = *(const float4*)&Xp[(size_t)(s + 3) * Dn];
        A0.x += w0 * x0.x; A0.y += w0 * x0.y; A0.z += w0 * x0.z; A0.w += w0 * x0.w;
        A1.x += w1 * x1.x; A1.y += w1 * x1.y; A1.z += w1 * x1.z; A1.w += w1 * x1.w;
    }
    for (; s < len; s += 3) {
        const float w0 = sc[s];
        const float4 x0 = *(const float4*)&Xp[(size_t)s * Dn];
        A0.x += w0 * x0.x; A0.y += w0 * x0.y; A0.z += w0 * x0.z; A0.w += w0 * x0.w;
    }
    float4 r;
    r.x = A0.x + A1.x; r.y = A0.y + A1.y; r.z = A0.z + A1.z; r.w = A0.w + A1.w;
    *(float4*)&pool[g][tg * 4] = r;
    __syncthreads();

    if (t < 192) {
        const int d = t * 4;
        const float4 p0 = *(const float4*)&pool[0][d];
        const float4 p1 = *(const float4*)&pool[1][d];
        const float4 p2 = *(const float4*)&pool[2][d];
        float sv[4];
        sv[0] = (p0.x + p1.x) + p2.x;
        sv[1] = (p0.y + p1.y) + p2.y;
        sv[2] = (p0.z + p1.z) + p2.z;
        sv[3] = (p0.w + p1.w) + p2.w;
        __nv_bfloat16 h[4], l[4];
        #pragma unroll
        for (int i = 0; i < 4; ++i) {
            h[i] = __float2bfloat16(sv[i]);
            l[i] = __float2bfloat16(sv[i] - __bfloat162float(h[i]));
        }
        *(uint2*)&g_featsH[(size_t)b * K2 + d] = *(uint2*)h;
        *(uint2*)&g_featsL[(size_t)b * K2 + d] = *(uint2*)l;
    }
}

// ---------------------------------------------------------------------------
// kB: bf16 tensor-core GEMM (split-bf16 emulated fp32), cp.async 2-stage,
// Block 64(M) x 64(N), BK=32, 128 thr = 4 warps, KSPLIT=16. (R9 version)
// ---------------------------------------------------------------------------
#define LDK 40   // 80B rows, conflict-free ldmatrix

__device__ __forceinline__ void mma_bf16(
    float* c, const unsigned* a, const unsigned* b)
{
    asm volatile(
        "mma.sync.aligned.m16n8k16.row.col.f32.bf16.bf16.f32 "
        "{%0,%1,%2,%3}, {%4,%5,%6,%7}, {%8,%9}, {%0,%1,%2,%3};"
        : "+f"(c[0]), "+f"(c[1]), "+f"(c[2]), "+f"(c[3])
        : "r"(a[0]), "r"(a[1]), "r"(a[2]), "r"(a[3]), "r"(b[0]), "r"(b[1]));
}

__device__ __forceinline__ void ldsm4(unsigned* r, unsigned addr)
{
    asm volatile("ldmatrix.sync.aligned.m8n8.x4.shared.b16 {%0,%1,%2,%3}, [%4];"
                 : "=r"(r[0]), "=r"(r[1]), "=r"(r[2]), "=r"(r[3]) : "r"(addr));
}

__device__ __forceinline__ void cp16(void* dst, const void* src)
{
    const unsigned d = (unsigned)__cvta_generic_to_shared(dst);
    asm volatile("cp.async.ca.shared.global [%0], [%1], 16;" :: "r"(d), "l"(src));
}

__global__ __launch_bounds__(128) void kB()
{
    __shared__ __nv_bfloat16 smem[2][4][64 * LDK];

    const int t = threadIdx.x;
    const int warp = t >> 5, lane = t & 31;
    const int bn = blockIdx.x * 64;
    const int bm = blockIdx.y * 64;
    const int kbase = blockIdx.z * KCH;
    const int wm = warp & 1, wn = warp >> 1;

    float acc[2][4][4] = {};

    const int row = t >> 2;
    const int cq  = (t & 3) * 8;

    #define ISSUE(it, stg) do {                                                   \
        const int kg = kbase + (it) * 32;                                          \
        _Pragma("unroll")                                                          \
        for (int i = 0; i < 2; ++i) {                                              \
            const int r = row + i * 32;                                            \
            cp16(&smem[stg][0][r * LDK + cq], &g_featsH[(size_t)(bm + r) * K2 + kg + cq]); \
            cp16(&smem[stg][1][r * LDK + cq], &g_featsL[(size_t)(bm + r) * K2 + kg + cq]); \
            cp16(&smem[stg][2][r * LDK + cq], &g_WH[(size_t)(bn + r) * K2 + kg + cq]);     \
            cp16(&smem[stg][3][r * LDK + cq], &g_WL[(size_t)(bn + r) * K2 + kg + cq]);     \
        }                                                                          \
        asm volatile("cp.async.commit_group;");                                    \
    } while (0)

    ISSUE(0, 0);

    for (int it = 0; it < NIT; ++it) {
        const int stg = it & 1;
        if (it + 1 < NIT) {
            ISSUE(it + 1, stg ^ 1);
            asm volatile("cp.async.wait_group 1;");
        } else {
            asm volatile("cp.async.wait_group 0;");
        }
        __syncthreads();

        const unsigned ah_b = (unsigned)__cvta_generic_to_shared(smem[stg][0]);
        const unsigned al_b = (unsigned)__cvta_generic_to_shared(smem[stg][1]);
        const unsigned bh_b = (unsigned)__cvta_generic_to_shared(smem[stg][2]);
        const unsigned bl_b = (unsigned)__cvta_generic_to_shared(smem[stg][3]);

        #pragma unroll
        for (int kk = 0; kk < 32; kk += 16) {
            unsigned Ah[2][4], Al[2][4];
            #pragma unroll
            for (int tm = 0; tm < 2; ++tm) {
                const unsigned off =
                    (unsigned)(((wm * 32 + tm * 16 + (lane & 15)) * LDK
                               + kk + (lane >> 4) * 8) * 2);
                ldsm4(Ah[tm], ah_b + off);
                ldsm4(Al[tm], al_b + off);
            }
            unsigned Bh[4][2], Bl[4][2];
            #pragma unroll
            for (int bj = 0; bj < 2; ++bj) {
                const int quad = lane >> 3, l8 = lane & 7;
                const int n = wn * 32 + bj * 16 + (quad >> 1) * 8 + l8;
                const int k = kk + (quad & 1) * 8;
                const unsigned off = (unsigned)((n * LDK + k) * 2);
                unsigned r4[4];
                ldsm4(r4, bh_b + off);
                Bh[bj * 2][0] = r4[0]; Bh[bj * 2][1] = r4[1];
                Bh[bj * 2 + 1][0] = r4[2]; Bh[bj * 2 + 1][1] = r4[3];
                ldsm4(r4, bl_b + off);
                Bl[bj * 2][0] = r4[0]; Bl[bj * 2][1] = r4[1];
                Bl[bj * 2 + 1][0] = r4[2]; Bl[bj * 2 + 1][1] = r4[3];
            }
            #pragma unroll
            for (int tm = 0; tm < 2; ++tm)
                #pragma unroll
                for (int tn = 0; tn < 4; ++tn) {
                    mma_bf16(acc[tm][tn], Ah[tm], Bh[tn]);
                    mma_bf16(acc[tm][tn], Ah[tm], Bl[tn]);
                    mma_bf16(acc[tm][tn], Al[tm], Bh[tn]);
                }
        }
        __syncthreads();
    }

    float* P = g_part[blockIdx.z];
    const int r0 = bm + wm * 32 + (lane >> 2);
    const int c0 = bn + wn * 32 + (lane & 3) * 2;
    #pragma unroll
    for (int tm = 0; tm < 2; ++tm)
        #pragma unroll
        for (int tn = 0; tn < 4; ++tn) {
            const int r = r0 + tm * 16;
            const int c = c0 + tn * 8;
            *(float2*)&P[(size_t)r * Dn + c]       = make_float2(acc[tm][tn][0], acc[tm][tn][1]);
            *(float2*)&P[(size_t)(r + 8) * Dn + c] = make_float2(acc[tm][tn][2], acc[tm][tn][3]);
        }
}

// ---------------------------------------------------------------------------
// kH: split-K reduce + bias + tanh, HIGH PARALLELISM: 768 blocks x 256 thr,
// one scalar element per thread, 16 coalesced independent loads (MLP=16).
// ---------------------------------------------------------------------------
__global__ __launch_bounds__(256) void kH(const float* __restrict__ bd)
{
    const int i = blockIdx.x * 256 + threadIdx.x;   // over Bn*Dn = 768*256
    float p[KSPLIT];
    #pragma unroll
    for (int k = 0; k < KSPLIT; ++k) p[k] = g_part[k][i];
    float s = bd[i % Dn];
    #pragma unroll
    for (int k = 0; k < KSPLIT; ++k) s += p[k];
    g_h[i] = tanhf(s);
}

// ---------------------------------------------------------------------------
// kC: decoder + mixes; 768 thr = 24 warps, ONE row j per warp (21 used).
// ---------------------------------------------------------------------------
__global__ __launch_bounds__(768) void kC(
    const float* __restrict__ dec_w,
    const float* __restrict__ dec_b,
    const float* __restrict__ w0,
    const float* __restrict__ w1,
    const float* __restrict__ w2,
    float*       __restrict__ out)
{
    const int b = blockIdx.x;
    const int t = threadIdx.x;
    const int warp = t >> 5, lane = t & 31;

    __shared__ float hs[Dn];
    __shared__ float probs[21];

    if (t < 192) *(float4*)&hs[t * 4] = *(const float4*)&g_h[(size_t)b * Dn + t * 4];
    __syncthreads();

    if (warp < 21) {
        const int v = c_ids[warp];
        const float* rw = dec_w + (size_t)v * Dn;
        float s = 0.f;
        #pragma unroll
        for (int j = 0; j < 6; ++j) {
            const int d = j * 128 + lane * 4;
            const float4 h4 = *(const float4*)&hs[d];
            const float4 r4 = *(const float4*)&rw[d];
            s += h4.x * r4.x + h4.y * r4.y + h4.z * r4.z + h4.w * r4.w;
        }
        #pragma unroll
        for (int o = 16; o > 0; o >>= 1) s += __shfl_xor_sync(0xffffffffu, s, o);
        if (lane == 0) probs[warp] = tanhf(s + dec_b[v]);
    }
    __syncthreads();

    if (t < 6) {
        const int o = t / 3, g = t % 3;
        const float* w = (g == 0) ? w0 : (g == 1) ? w1 : w2;
        const int off = (g == 0) ? 0 : (g == 1) ? 8 : 14;
        const int n   = (g == 0) ? 8 : (g == 1) ? 6 : 7;
        float s = 0.f;
        for (int j = 0; j < n; ++j) s += probs[off + j] * w[o * n + j];
        out[2 * Bn + b * 6 + o * 3 + g] = s;
    }
}

// ---------------------------------------------------------------------------
extern "C" void kernel_launch(void* const* d_in, const int* in_sizes, int n_in,
                              void* d_out, int out_size)
{
    const float* bert    = (const float*)d_in[0];
    const int*   ids     = (const int*)  d_in[1];
    const int*   length  = (const int*)  d_in[2];
    const float* senti_w = (const float*)d_in[3];
    const float* senti_b = (const float*)d_in[4];
    const float* dense_w = (const float*)d_in[5];
    const float* dense_b = (const float*)d_in[6];
    const float* dec_w   = (const float*)d_in[7];
    const float* dec_b   = (const float*)d_in[8];
    const float* w0      = (const float*)d_in[9];
    const float* w1      = (const float*)d_in[10];
    const float* w2      = (const float*)d_in[11];
    float* out = (float*)d_out;

    kW<<<(Dn * K2) / 1024, 256>>>(dense_w);
    kA<<<Bn, 576>>>(bert, ids, length, senti_w, senti_b, out);
    kB<<<dim3(Dn / 64, Bn / 64, KSPLIT), 128>>>();
    kH<<<(Bn * Dn) / 256, 256>>>(dense_b);
    kC<<<Bn, 768>>>(dec_w, dec_b, w0, w1, w2, out);
}

// round 13
// speedup vs baseline: 1.2802x; 1.0069x over previous
#include <cuda_runtime.h>
#include <cuda_bf16.h>
#include <math.h>

#define Bn 256
#define Sn 128
#define Dn 768
#define K2 1536
#define MASK_ID 103
#define KSPLIT 16
#define KCH (K2 / KSPLIT)   // 96
#define NIT (KCH / 32)      // 3
#define NWB ((Dn * K2) / 1024)   // 1152 blocks for W-split

// Scratch (__device__ globals; no allocs allowed)
__device__ __nv_bfloat16 g_featsH[Bn * K2];     // feats bf16 hi
__device__ __nv_bfloat16 g_featsL[Bn * K2];     // feats bf16 lo
__device__ __nv_bfloat16 g_WH[Dn * K2];         // dense_w bf16 hi
__device__ __nv_bfloat16 g_WL[Dn * K2];         // dense_w bf16 lo
__device__ float g_part[KSPLIT][Bn * Dn];       // split-K partials

static __device__ const int c_ids[21] = {
    2307, 2204, 3835, 2157, 6581, 2986, 5151, 3893,
    7929, 24791, 8699, 4257, 16021, 6623,
    6659, 2919, 11771, 3532, 11325, 4997, 13135
};

__device__ __forceinline__ void split_store(
    __nv_bfloat16* ph, __nv_bfloat16* pl, float v)
{
    const __nv_bfloat16 h = __float2bfloat16(v);
    *ph = h;
    *pl = __float2bfloat16(v - __bfloat162float(h));
}

// ---------------------------------------------------------------------------
// kWA: fused pre-work.
//  blocks [0, NWB): dense_w bf16 hi/lo split (1024 floats/block, 256 thr used)
//  blocks [NWB, NWB+Bn): fused per-batch attention stage (576 thr)
// ---------------------------------------------------------------------------
__global__ __launch_bounds__(576) void kWA(
    const float* __restrict__ Wd,
    const float* __restrict__ bert,
    const int*   __restrict__ ids,
    const int*   __restrict__ length,
    const float* __restrict__ senti_w,
    const float* __restrict__ senti_b,
    float*       __restrict__ out)
{
    const int t = threadIdx.x;

    if (blockIdx.x < NWB) {
        if (t < 256) {
            const int i = (blockIdx.x * 256 + t) * 4;
            const float4 v = *(const float4*)&Wd[i];
            __nv_bfloat16 h[4], l[4];
            h[0] = __float2bfloat16(v.x); l[0] = __float2bfloat16(v.x - __bfloat162float(h[0]));
            h[1] = __float2bfloat16(v.y); l[1] = __float2bfloat16(v.y - __bfloat162float(h[1]));
            h[2] = __float2bfloat16(v.z); l[2] = __float2bfloat16(v.z - __bfloat162float(h[2]));
            h[3] = __float2bfloat16(v.w); l[3] = __float2bfloat16(v.w - __bfloat162float(h[3]));
            *(uint2*)&g_WH[i] = *(uint2*)h;
            *(uint2*)&g_WL[i] = *(uint2*)l;
        }
        return;
    }

    const int b = blockIdx.x - NWB;
    const int warp = t >> 5, lane = t & 31;
    const int len = length[b];

    __shared__ float ml[Dn];
    __shared__ float sc[112];
    __shared__ float pool[3][Dn];
    __shared__ float red[18];
    __shared__ int   mp_s;

    if (t < Sn && ids[b * Sn + t] == MASK_ID) mp_s = t;
    __syncthreads();
    const int mp = mp_s;
    const float* Xb = bert + (size_t)b * Sn * Dn;

    for (int d = t; d < Dn; d += 576) {
        const float v = Xb[(size_t)mp * Dn + d];
        ml[d] = v;
        split_store(&g_featsH[(size_t)b * K2 + Dn + d],
                    &g_featsL[(size_t)b * K2 + Dn + d], v);
    }
    __syncthreads();

    // category head (pooler = row 0), warps 16/17
    if (warp >= 16) {
        const int c = warp - 16;
        float s = 0.f;
        for (int d = lane * 4; d < Dn; d += 128) {
            const float4 x = *(const float4*)&Xb[d];
            const float4 w = *(const float4*)&senti_w[c * Dn + d];
            s += x.x * w.x + x.y * w.y + x.z * w.z + x.w * w.w;
        }
        #pragma unroll
        for (int o = 16; o > 0; o >>= 1) s += __shfl_xor_sync(0xffffffffu, s, o);
        if (lane == 0) out[b * 2 + c] = s + senti_b[c];
    }

    for (int s = warp; s < len; s += 18) {
        const float* row = Xb + (size_t)(s + 3) * Dn;
        float acc = 0.f;
        #pragma unroll
        for (int j = 0; j < 6; ++j) {
            const int d = j * 128 + lane * 4;
            const float4 x = *(const float4*)&row[d];
            const float4 m = *(const float4*)&ml[d];
            acc += x.x * m.x + x.y * m.y + x.z * m.z + x.w * m.w;
        }
        #pragma unroll
        for (int o = 16; o > 0; o >>= 1) acc += __shfl_xor_sync(0xffffffffu, acc, o);
        if (lane == 0) sc[s] = acc;
    }
    __syncthreads();

    float v = (t < len) ? sc[t] : -INFINITY;
    float m = v;
    #pragma unroll
    for (int o = 16; o > 0; o >>= 1) m = fmaxf(m, __shfl_xor_sync(0xffffffffu, m, o));
    if (lane == 0) red[warp] = m;
    __syncthreads();
    m = red[0];
    #pragma unroll
    for (int i = 1; i < 18; ++i) m = fmaxf(m, red[i]);
    __syncthreads();

    float e = (t < len) ? __expf(v - m) : 0.f;
    float su = e;
    #pragma unroll
    for (int o = 16; o > 0; o >>= 1) su += __shfl_xor_sync(0xffffffffu, su, o);
    if (lane == 0) red[warp] = su;
    __syncthreads();
    su = 0.f;
    #pragma unroll
    for (int i = 0; i < 18; ++i) su += red[i];
    const float inv = 1.f / su;
    __syncthreads();
    if (t < len) sc[t] = e * inv;
    __syncthreads();

    const int g  = t / 192;
    const int tg = t - g * 192;
    const float* Xp = Xb + (size_t)3 * Dn + tg * 4;

    float4 A0 = {0,0,0,0}, A1 = {0,0,0,0};
    int s = g;
    for (; s + 3 < len; s += 6) {
        const float w0 = sc[s], w1 = sc[s + 3];
        const float4 x0 = *(const float4*)&Xp[(size_t)s * Dn];
        const float4 x1 = *(const float4*)&Xp[(size_t)(s + 3) * Dn];
        A0.x += w0 * x0.x; A0.y += w0 * x0.y; A0.z += w0 * x0.z; A0.w += w0 * x0.w;
        A1.x += w1 * x1.x; A1.y += w1 * x1.y; A1.z += w1 * x1.z; A1.w += w1 * x1.w;
    }
    for (; s < len; s += 3) {
        const float w0 = sc[s];
        const float4 x0 = *(const float4*)&Xp[(size_t)s * Dn];
        A0.x += w0 * x0.x; A0.y += w0 * x0.y; A0.z += w0 * x0.z; A0.w += w0 * x0.w;
    }
    float4 r;
    r.x = A0.x + A1.x; r.y = A0.y + A1.y; r.z = A0.z + A1.z; r.w = A0.w + A1.w;
    *(float4*)&pool[g][tg * 4] = r;
    __syncthreads();

    if (t < 192) {
        const int d = t * 4;
        const float4 p0 = *(const float4*)&pool[0][d];
        const float4 p1 = *(const float4*)&pool[1][d];
        const float4 p2 = *(const float4*)&pool[2][d];
        float sv[4];
        sv[0] = (p0.x + p1.x) + p2.x;
        sv[1] = (p0.y + p1.y) + p2.y;
        sv[2] = (p0.z + p1.z) + p2.z;
        sv[3] = (p0.w + p1.w) + p2.w;
        __nv_bfloat16 h[4], l[4];
        #pragma unroll
        for (int i = 0; i < 4; ++i) {
            h[i] = __float2bfloat16(sv[i]);
            l[i] = __float2bfloat16(sv[i] - __bfloat162float(h[i]));
        }
        *(uint2*)&g_featsH[(size_t)b * K2 + d] = *(uint2*)h;
        *(uint2*)&g_featsL[(size_t)b * K2 + d] = *(uint2*)l;
    }
}

// ---------------------------------------------------------------------------
// kB: bf16 tensor-core GEMM (split-bf16 emulated fp32), cp.async 2-stage,
// Block 64(M) x 64(N), BK=32, 128 thr = 4 warps, KSPLIT=16.
// ---------------------------------------------------------------------------
#define LDK 40   // 80B rows, conflict-free ldmatrix

__device__ __forceinline__ void mma_bf16(
    float* c, const unsigned* a, const unsigned* b)
{
    asm volatile(
        "mma.sync.aligned.m16n8k16.row.col.f32.bf16.bf16.f32 "
        "{%0,%1,%2,%3}, {%4,%5,%6,%7}, {%8,%9}, {%0,%1,%2,%3};"
        : "+f"(c[0]), "+f"(c[1]), "+f"(c[2]), "+f"(c[3])
        : "r"(a[0]), "r"(a[1]), "r"(a[2]), "r"(a[3]), "r"(b[0]), "r"(b[1]));
}

__device__ __forceinline__ void ldsm4(unsigned* r, unsigned addr)
{
    asm volatile("ldmatrix.sync.aligned.m8n8.x4.shared.b16 {%0,%1,%2,%3}, [%4];"
                 : "=r"(r[0]), "=r"(r[1]), "=r"(r[2]), "=r"(r[3]) : "r"(addr));
}

__device__ __forceinline__ void cp16(void* dst, const void* src)
{
    const unsigned d = (unsigned)__cvta_generic_to_shared(dst);
    asm volatile("cp.async.ca.shared.global [%0], [%1], 16;" :: "r"(d), "l"(src));
}

__global__ __launch_bounds__(128) void kB()
{
    __shared__ __nv_bfloat16 smem[2][4][64 * LDK];

    const int t = threadIdx.x;
    const int warp = t >> 5, lane = t & 31;
    const int bn = blockIdx.x * 64;
    const int bm = blockIdx.y * 64;
    const int kbase = blockIdx.z * KCH;
    const int wm = warp & 1, wn = warp >> 1;

    float acc[2][4][4] = {};

    const int row = t >> 2;
    const int cq  = (t & 3) * 8;

    #define ISSUE(it, stg) do {                                                   \
        const int kg = kbase + (it) * 32;                                          \
        _Pragma("unroll")                                                          \
        for (int i = 0; i < 2; ++i) {                                              \
            const int r = row + i * 32;                                            \
            cp16(&smem[stg][0][r * LDK + cq], &g_featsH[(size_t)(bm + r) * K2 + kg + cq]); \
            cp16(&smem[stg][1][r * LDK + cq], &g_featsL[(size_t)(bm + r) * K2 + kg + cq]); \
            cp16(&smem[stg][2][r * LDK + cq], &g_WH[(size_t)(bn + r) * K2 + kg + cq]);     \
            cp16(&smem[stg][3][r * LDK + cq], &g_WL[(size_t)(bn + r) * K2 + kg + cq]);     \
        }                                                                          \
        asm volatile("cp.async.commit_group;");                                    \
    } while (0)

    ISSUE(0, 0);

    for (int it = 0; it < NIT; ++it) {
        const int stg = it & 1;
        if (it + 1 < NIT) {
            ISSUE(it + 1, stg ^ 1);
            asm volatile("cp.async.wait_group 1;");
        } else {
            asm volatile("cp.async.wait_group 0;");
        }
        __syncthreads();

        const unsigned ah_b = (unsigned)__cvta_generic_to_shared(smem[stg][0]);
        const unsigned al_b = (unsigned)__cvta_generic_to_shared(smem[stg][1]);
        const unsigned bh_b = (unsigned)__cvta_generic_to_shared(smem[stg][2]);
        const unsigned bl_b = (unsigned)__cvta_generic_to_shared(smem[stg][3]);

        #pragma unroll
        for (int kk = 0; kk < 32; kk += 16) {
            unsigned Ah[2][4], Al[2][4];
            #pragma unroll
            for (int tm = 0; tm < 2; ++tm) {
                const unsigned off =
                    (unsigned)(((wm * 32 + tm * 16 + (lane & 15)) * LDK
                               + kk + (lane >> 4) * 8) * 2);
                ldsm4(Ah[tm], ah_b + off);
                ldsm4(Al[tm], al_b + off);
            }
            unsigned Bh[4][2], Bl[4][2];
            #pragma unroll
            for (int bj = 0; bj < 2; ++bj) {
                const int quad = lane >> 3, l8 = lane & 7;
                const int n = wn * 32 + bj * 16 + (quad >> 1) * 8 + l8;
                const int k = kk + (quad & 1) * 8;
                const unsigned off = (unsigned)((n * LDK + k) * 2);
                unsigned r4[4];
                ldsm4(r4, bh_b + off);
                Bh[bj * 2][0] = r4[0]; Bh[bj * 2][1] = r4[1];
                Bh[bj * 2 + 1][0] = r4[2]; Bh[bj * 2 + 1][1] = r4[3];
                ldsm4(r4, bl_b + off);
                Bl[bj * 2][0] = r4[0]; Bl[bj * 2][1] = r4[1];
                Bl[bj * 2 + 1][0] = r4[2]; Bl[bj * 2 + 1][1] = r4[3];
            }
            #pragma unroll
            for (int tm = 0; tm < 2; ++tm)
                #pragma unroll
                for (int tn = 0; tn < 4; ++tn) {
                    mma_bf16(acc[tm][tn], Ah[tm], Bh[tn]);
                    mma_bf16(acc[tm][tn], Ah[tm], Bl[tn]);
                    mma_bf16(acc[tm][tn], Al[tm], Bh[tn]);
                }
        }
        __syncthreads();
    }

    float* P = g_part[blockIdx.z];
    const int r0 = bm + wm * 32 + (lane >> 2);
    const int c0 = bn + wn * 32 + (lane & 3) * 2;
    #pragma unroll
    for (int tm = 0; tm < 2; ++tm)
        #pragma unroll
        for (int tn = 0; tn < 4; ++tn) {
            const int r = r0 + tm * 16;
            const int c = c0 + tn * 8;
            *(float2*)&P[(size_t)r * Dn + c]       = make_float2(acc[tm][tn][0], acc[tm][tn][1]);
            *(float2*)&P[(size_t)(r + 8) * Dn + c] = make_float2(acc[tm][tn][2], acc[tm][tn][3]);
        }
}

// ---------------------------------------------------------------------------
// kCH: fused split-K reduce + bias + tanh + decoder + mixes.
// 256 blocks x 768 thr (24 warps => same chip-wide warp count as kH had).
// Reduce: thread t owns element d=t, 16 coalesced independent partial loads.
// Decode: warps 0..20 each own ONE decoder row.
// ---------------------------------------------------------------------------
__global__ __launch_bounds__(768) void kCH(
    const float* __restrict__ dense_b,
    const float* __restrict__ dec_w,
    const float* __restrict__ dec_b,
    const float* __restrict__ w0,
    const float* __restrict__ w1,
    const float* __restrict__ w2,
    float*       __restrict__ out)
{
    const int b = blockIdx.x;
    const int t = threadIdx.x;
    const int warp = t >> 5, lane = t & 31;

    __shared__ float hs[Dn];
    __shared__ float probs[21];

    {
        const size_t gi = (size_t)b * Dn + t;
        float p[KSPLIT];
        #pragma unroll
        for (int k = 0; k < KSPLIT; ++k) p[k] = g_part[k][gi];
        float s = dense_b[t];
        #pragma unroll
        for (int k = 0; k < KSPLIT; ++k) s += p[k];
        hs[t] = tanhf(s);
    }
    __syncthreads();

    if (warp < 21) {
        const int v = c_ids[warp];
        const float* rw = dec_w + (size_t)v * Dn;
        float s = 0.f;
        #pragma unroll
        for (int j = 0; j < 6; ++j) {
            const int d = j * 128 + lane * 4;
            const float4 h4 = *(const float4*)&hs[d];
            const float4 r4 = *(const float4*)&rw[d];
            s += h4.x * r4.x + h4.y * r4.y + h4.z * r4.z + h4.w * r4.w;
        }
        #pragma unroll
        for (int o = 16; o > 0; o >>= 1) s += __shfl_xor_sync(0xffffffffu, s, o);
        if (lane == 0) probs[warp] = tanhf(s + dec_b[v]);
    }
    __syncthreads();

    if (t < 6) {
        const int o = t / 3, g = t % 3;
        const float* w = (g == 0) ? w0 : (g == 1) ? w1 : w2;
        const int off = (g == 0) ? 0 : (g == 1) ? 8 : 14;
        const int n   = (g == 0) ? 8 : (g == 1) ? 6 : 7;
        float s = 0.f;
        for (int j = 0; j < n; ++j) s += probs[off + j] * w[o * n + j];
        out[2 * Bn + b * 6 + o * 3 + g] = s;
    }
}

// ---------------------------------------------------------------------------
extern "C" void kernel_launch(void* const* d_in, const int* in_sizes, int n_in,
                              void* d_out, int out_size)
{
    const float* bert    = (const float*)d_in[0];
    const int*   ids     = (const int*)  d_in[1];
    const int*   length  = (const int*)  d_in[2];
    const float* senti_w = (const float*)d_in[3];
    const float* senti_b = (const float*)d_in[4];
    const float* dense_w = (const float*)d_in[5];
    const float* dense_b = (const float*)d_in[6];
    const float* dec_w   = (const float*)d_in[7];
    const float* dec_b   = (const float*)d_in[8];
    const float* w0      = (const float*)d_in[9];
    const float* w1      = (const float*)d_in[10];
    const float* w2      = (const float*)d_in[11];
    float* out = (float*)d_out;

    kWA<<<NWB + Bn, 576>>>(dense_w, bert, ids, length, senti_w, senti_b, out);
    kB <<<dim3(Dn / 64, Bn / 64, KSPLIT), 128>>>();
    kCH<<<Bn, 768>>>(dense_b, dec_w, dec_b, w0, w1, w2, out);
}

// round 14
// speedup vs baseline: 1.2958x; 1.0121x over previous
#include <cuda_runtime.h>
#include <cuda_bf16.h>
#include <math.h>

#define Bn 256
#define Sn 128
#define Dn 768
#define K2 1536
#define MASK_ID 103
#define KSPLIT 16
#define KCH (K2 / KSPLIT)   // 96
#define NIT (KCH / 32)      // 3
#define NWB ((Dn * K2) / (576 * 4))   // 512 blocks for W-split (all 576 thr used)

// Scratch (__device__ globals; no allocs allowed)
__device__ __nv_bfloat16 g_featsH[Bn * K2];     // feats bf16 hi
__device__ __nv_bfloat16 g_featsL[Bn * K2];     // feats bf16 lo
__device__ __nv_bfloat16 g_WH[Dn * K2];         // dense_w bf16 hi
__device__ __nv_bfloat16 g_WL[Dn * K2];         // dense_w bf16 lo
__device__ float g_part[KSPLIT][Bn * Dn];       // split-K partials

static __device__ const int c_ids[21] = {
    2307, 2204, 3835, 2157, 6581, 2986, 5151, 3893,
    7929, 24791, 8699, 4257, 16021, 6623,
    6659, 2919, 11771, 3532, 11325, 4997, 13135
};

__device__ __forceinline__ void split_store(
    __nv_bfloat16* ph, __nv_bfloat16* pl, float v)
{
    const __nv_bfloat16 h = __float2bfloat16(v);
    *ph = h;
    *pl = __float2bfloat16(v - __bfloat162float(h));
}

// ---------------------------------------------------------------------------
// kWA: fused pre-work.
//  blocks [0, NWB): dense_w bf16 hi/lo split — ALL 576 threads used
//  blocks [NWB, NWB+Bn): fused per-batch attention stage (576 thr)
// ---------------------------------------------------------------------------
__global__ __launch_bounds__(576) void kWA(
    const float* __restrict__ Wd,
    const float* __restrict__ bert,
    const int*   __restrict__ ids,
    const int*   __restrict__ length,
    const float* __restrict__ senti_w,
    const float* __restrict__ senti_b,
    float*       __restrict__ out)
{
    const int t = threadIdx.x;

    if (blockIdx.x < NWB) {
        const int i = (blockIdx.x * 576 + t) * 4;
        const float4 v = *(const float4*)&Wd[i];
        __nv_bfloat16 h[4], l[4];
        h[0] = __float2bfloat16(v.x); l[0] = __float2bfloat16(v.x - __bfloat162float(h[0]));
        h[1] = __float2bfloat16(v.y); l[1] = __float2bfloat16(v.y - __bfloat162float(h[1]));
        h[2] = __float2bfloat16(v.z); l[2] = __float2bfloat16(v.z - __bfloat162float(h[2]));
        h[3] = __float2bfloat16(v.w); l[3] = __float2bfloat16(v.w - __bfloat162float(h[3]));
        *(uint2*)&g_WH[i] = *(uint2*)h;
        *(uint2*)&g_WL[i] = *(uint2*)l;
        return;
    }

    const int b = blockIdx.x - NWB;
    const int warp = t >> 5, lane = t & 31;
    const int len = length[b];

    __shared__ float ml[Dn];
    __shared__ float sc[112];
    __shared__ float pool[3][Dn];
    __shared__ float red[18];
    __shared__ int   mp_s;

    if (t < Sn && ids[b * Sn + t] == MASK_ID) mp_s = t;
    __syncthreads();
    const int mp = mp_s;
    const float* Xb = bert + (size_t)b * Sn * Dn;

    for (int d = t; d < Dn; d += 576) {
        const float v = Xb[(size_t)mp * Dn + d];
        ml[d] = v;
        split_store(&g_featsH[(size_t)b * K2 + Dn + d],
                    &g_featsL[(size_t)b * K2 + Dn + d], v);
    }
    __syncthreads();

    // category head (pooler = row 0), warps 16/17
    if (warp >= 16) {
        const int c = warp - 16;
        float s = 0.f;
        for (int d = lane * 4; d < Dn; d += 128) {
            const float4 x = *(const float4*)&Xb[d];
            const float4 w = *(const float4*)&senti_w[c * Dn + d];
            s += x.x * w.x + x.y * w.y + x.z * w.z + x.w * w.w;
        }
        #pragma unroll
        for (int o = 16; o > 0; o >>= 1) s += __shfl_xor_sync(0xffffffffu, s, o);
        if (lane == 0) out[b * 2 + c] = s + senti_b[c];
    }

    // scores: 2 rows per warp iteration (12 independent loads in flight)
    for (int s0 = warp; s0 < len; s0 += 36) {
        const int s1 = s0 + 18;
        const bool has1 = (s1 < len);
        const float* r0 = Xb + (size_t)(s0 + 3) * Dn;
        const float* r1 = has1 ? (Xb + (size_t)(s1 + 3) * Dn) : r0;
        float a0 = 0.f, a1 = 0.f;
        #pragma unroll
        for (int j = 0; j < 6; ++j) {
            const int d = j * 128 + lane * 4;
            const float4 m  = *(const float4*)&ml[d];
            const float4 x0 = *(const float4*)&r0[d];
            const float4 x1 = *(const float4*)&r1[d];
            a0 += x0.x * m.x + x0.y * m.y + x0.z * m.z + x0.w * m.w;
            a1 += x1.x * m.x + x1.y * m.y + x1.z * m.z + x1.w * m.w;
        }
        #pragma unroll
        for (int o = 16; o > 0; o >>= 1) {
            a0 += __shfl_xor_sync(0xffffffffu, a0, o);
            a1 += __shfl_xor_sync(0xffffffffu, a1, o);
        }
        if (lane == 0) {
            sc[s0] = a0;
            if (has1) sc[s1] = a1;
        }
    }
    __syncthreads();

    float v = (t < len) ? sc[t] : -INFINITY;
    float m = v;
    #pragma unroll
    for (int o = 16; o > 0; o >>= 1) m = fmaxf(m, __shfl_xor_sync(0xffffffffu, m, o));
    if (lane == 0) red[warp] = m;
    __syncthreads();
    m = red[0];
    #pragma unroll
    for (int i = 1; i < 18; ++i) m = fmaxf(m, red[i]);
    __syncthreads();

    float e = (t < len) ? __expf(v - m) : 0.f;
    float su = e;
    #pragma unroll
    for (int o = 16; o > 0; o >>= 1) su += __shfl_xor_sync(0xffffffffu, su, o);
    if (lane == 0) red[warp] = su;
    __syncthreads();
    su = 0.f;
    #pragma unroll
    for (int i = 0; i < 18; ++i) su += red[i];
    const float inv = 1.f / su;
    __syncthreads();
    if (t < len) sc[t] = e * inv;
    __syncthreads();

    const int g  = t / 192;
    const int tg = t - g * 192;
    const float* Xp = Xb + (size_t)3 * Dn + tg * 4;

    float4 A0 = {0,0,0,0}, A1 = {0,0,0,0};
    int s = g;
    for (; s + 3 < len; s += 6) {
        const float w0 = sc[s], w1 = sc[s + 3];
        const float4 x0 = *(const float4*)&Xp[(size_t)s * Dn];
        const float4 x1 = *(const float4*)&Xp[(size_t)(s + 3) * Dn];
        A0.x += w0 * x0.x; A0.y += w0 * x0.y; A0.z += w0 * x0.z; A0.w += w0 * x0.w;
        A1.x += w1 * x1.x; A1.y += w1 * x1.y; A1.z += w1 * x1.z; A1.w += w1 * x1.w;
    }
    for (; s < len; s += 3) {
        const float w0 = sc[s];
        const float4 x0 = *(const float4*)&Xp[(size_t)s * Dn];
        A0.x += w0 * x0.x; A0.y += w0 * x0.y; A0.z += w0 * x0.z; A0.w += w0 * x0.w;
    }
    float4 r;
    r.x = A0.x + A1.x; r.y = A0.y + A1.y; r.z = A0.z + A1.z; r.w = A0.w + A1.w;
    *(float4*)&pool[g][tg * 4] = r;
    __syncthreads();

    if (t < 192) {
        const int d = t * 4;
        const float4 p0 = *(const float4*)&pool[0][d];
        const float4 p1 = *(const float4*)&pool[1][d];
        const float4 p2 = *(const float4*)&pool[2][d];
        float sv[4];
        sv[0] = (p0.x + p1.x) + p2.x;
        sv[1] = (p0.y + p1.y) + p2.y;
        sv[2] = (p0.z + p1.z) + p2.z;
        sv[3] = (p0.w + p1.w) + p2.w;
        __nv_bfloat16 h[4], l[4];
        #pragma unroll
        for (int i = 0; i < 4; ++i) {
            h[i] = __float2bfloat16(sv[i]);
            l[i] = __float2bfloat16(sv[i] - __bfloat162float(h[i]));
        }
        *(uint2*)&g_featsH[(size_t)b * K2 + d] = *(uint2*)h;
        *(uint2*)&g_featsL[(size_t)b * K2 + d] = *(uint2*)l;
    }
}

// ---------------------------------------------------------------------------
// kB: bf16 tensor-core GEMM (split-bf16 emulated fp32), cp.async 2-stage,
// Block 64(M) x 64(N), BK=32, 128 thr = 4 warps, KSPLIT=16.
// ---------------------------------------------------------------------------
#define LDK 40   // 80B rows, conflict-free ldmatrix

__device__ __forceinline__ void mma_bf16(
    float* c, const unsigned* a, const unsigned* b)
{
    asm volatile(
        "mma.sync.aligned.m16n8k16.row.col.f32.bf16.bf16.f32 "
        "{%0,%1,%2,%3}, {%4,%5,%6,%7}, {%8,%9}, {%0,%1,%2,%3};"
        : "+f"(c[0]), "+f"(c[1]), "+f"(c[2]), "+f"(c[3])
        : "r"(a[0]), "r"(a[1]), "r"(a[2]), "r"(a[3]), "r"(b[0]), "r"(b[1]));
}

__device__ __forceinline__ void ldsm4(unsigned* r, unsigned addr)
{
    asm volatile("ldmatrix.sync.aligned.m8n8.x4.shared.b16 {%0,%1,%2,%3}, [%4];"
                 : "=r"(r[0]), "=r"(r[1]), "=r"(r[2]), "=r"(r[3]) : "r"(addr));
}

__device__ __forceinline__ void cp16(void* dst, const void* src)
{
    const unsigned d = (unsigned)__cvta_generic_to_shared(dst);
    asm volatile("cp.async.ca.shared.global [%0], [%1], 16;" :: "r"(d), "l"(src));
}

__global__ __launch_bounds__(128) void kB()
{
    __shared__ __nv_bfloat16 smem[2][4][64 * LDK];

    const int t = threadIdx.x;
    const int warp = t >> 5, lane = t & 31;
    const int bn = blockIdx.x * 64;
    const int bm = blockIdx.y * 64;
    const int kbase = blockIdx.z * KCH;
    const int wm = warp & 1, wn = warp >> 1;

    float acc[2][4][4] = {};

    const int row = t >> 2;
    const int cq  = (t & 3) * 8;

    #define ISSUE(it, stg) do {                                                   \
        const int kg = kbase + (it) * 32;                                          \
        _Pragma("unroll")                                                          \
        for (int i = 0; i < 2; ++i) {                                              \
            const int r = row + i * 32;                                            \
            cp16(&smem[stg][0][r * LDK + cq], &g_featsH[(size_t)(bm + r) * K2 + kg + cq]); \
            cp16(&smem[stg][1][r * LDK + cq], &g_featsL[(size_t)(bm + r) * K2 + kg + cq]); \
            cp16(&smem[stg][2][r * LDK + cq], &g_WH[(size_t)(bn + r) * K2 + kg + cq]);     \
            cp16(&smem[stg][3][r * LDK + cq], &g_WL[(size_t)(bn + r) * K2 + kg + cq]);     \
        }                                                                          \
        asm volatile("cp.async.commit_group;");                                    \
    } while (0)

    ISSUE(0, 0);

    for (int it = 0; it < NIT; ++it) {
        const int stg = it & 1;
        if (it + 1 < NIT) {
            ISSUE(it + 1, stg ^ 1);
            asm volatile("cp.async.wait_group 1;");
        } else {
            asm volatile("cp.async.wait_group 0;");
        }
        __syncthreads();

        const unsigned ah_b = (unsigned)__cvta_generic_to_shared(smem[stg][0]);
        const unsigned al_b = (unsigned)__cvta_generic_to_shared(smem[stg][1]);
        const unsigned bh_b = (unsigned)__cvta_generic_to_shared(smem[stg][2]);
        const unsigned bl_b = (unsigned)__cvta_generic_to_shared(smem[stg][3]);

        #pragma unroll
        for (int kk = 0; kk < 32; kk += 16) {
            unsigned Ah[2][4], Al[2][4];
            #pragma unroll
            for (int tm = 0; tm < 2; ++tm) {
                const unsigned off =
                    (unsigned)(((wm * 32 + tm * 16 + (lane & 15)) * LDK
                               + kk + (lane >> 4) * 8) * 2);
                ldsm4(Ah[tm], ah_b + off);
                ldsm4(Al[tm], al_b + off);
            }
            unsigned Bh[4][2], Bl[4][2];
            #pragma unroll
            for (int bj = 0; bj < 2; ++bj) {
                const int quad = lane >> 3, l8 = lane & 7;
                const int n = wn * 32 + bj * 16 + (quad >> 1) * 8 + l8;
                const int k = kk + (quad & 1) * 8;
                const unsigned off = (unsigned)((n * LDK + k) * 2);
                unsigned r4[4];
                ldsm4(r4, bh_b + off);
                Bh[bj * 2][0] = r4[0]; Bh[bj * 2][1] = r4[1];
                Bh[bj * 2 + 1][0] = r4[2]; Bh[bj * 2 + 1][1] = r4[3];
                ldsm4(r4, bl_b + off);
                Bl[bj * 2][0] = r4[0]; Bl[bj * 2][1] = r4[1];
                Bl[bj * 2 + 1][0] = r4[2]; Bl[bj * 2 + 1][1] = r4[3];
            }
            #pragma unroll
            for (int tm = 0; tm < 2; ++tm)
                #pragma unroll
                for (int tn = 0; tn < 4; ++tn) {
                    mma_bf16(acc[tm][tn], Ah[tm], Bh[tn]);
                    mma_bf16(acc[tm][tn], Ah[tm], Bl[tn]);
                    mma_bf16(acc[tm][tn], Al[tm], Bh[tn]);
                }
        }
        __syncthreads();
    }

    float* P = g_part[blockIdx.z];
    const int r0 = bm + wm * 32 + (lane >> 2);
    const int c0 = bn + wn * 32 + (lane & 3) * 2;
    #pragma unroll
    for (int tm = 0; tm < 2; ++tm)
        #pragma unroll
        for (int tn = 0; tn < 4; ++tn) {
            const int r = r0 + tm * 16;
            const int c = c0 + tn * 8;
            *(float2*)&P[(size_t)r * Dn + c]       = make_float2(acc[tm][tn][0], acc[tm][tn][1]);
            *(float2*)&P[(size_t)(r + 8) * Dn + c] = make_float2(acc[tm][tn][2], acc[tm][tn][3]);
        }
}

// ---------------------------------------------------------------------------
// kCH: fused split-K reduce + bias + tanh + decoder + mixes.
// 256 blocks x 768 thr; thread t reduces element d=t (16 coalesced loads).
// Decode: warps 0..20 each own ONE decoder row.
// ---------------------------------------------------------------------------
__global__ __launch_bounds__(768) void kCH(
    const float* __restrict__ dense_b,
    const float* __restrict__ dec_w,
    const float* __restrict__ dec_b,
    const float* __restrict__ w0,
    const float* __restrict__ w1,
    const float* __restrict__ w2,
    float*       __restrict__ out)
{
    const int b = blockIdx.x;
    const int t = threadIdx.x;
    const int warp = t >> 5, lane = t & 31;

    __shared__ float hs[Dn];
    __shared__ float probs[21];

    {
        const size_t gi = (size_t)b * Dn + t;
        float p[KSPLIT];
        #pragma unroll
        for (int k = 0; k < KSPLIT; ++k) p[k] = g_part[k][gi];
        float s = dense_b[t];
        #pragma unroll
        for (int k = 0; k < KSPLIT; ++k) s += p[k];
        hs[t] = tanhf(s);
    }
    __syncthreads();

    if (warp < 21) {
        const int v = c_ids[warp];
        const float* rw = dec_w + (size_t)v * Dn;
        float s = 0.f;
        #pragma unroll
        for (int j = 0; j < 6; ++j) {
            const int d = j * 128 + lane * 4;
            const float4 h4 = *(const float4*)&hs[d];
            const float4 r4 = *(const float4*)&rw[d];
            s += h4.x * r4.x + h4.y * r4.y + h4.z * r4.z + h4.w * r4.w;
        }
        #pragma unroll
        for (int o = 16; o > 0; o >>= 1) s += __shfl_xor_sync(0xffffffffu, s, o);
        if (lane == 0) probs[warp] = tanhf(s + dec_b[v]);
    }
    __syncthreads();

    if (t < 6) {
        const int o = t / 3, g = t % 3;
        const float* w = (g == 0) ? w0 : (g == 1) ? w1 : w2;
        const int off = (g == 0) ? 0 : (g == 1) ? 8 : 14;
        const int n   = (g == 0) ? 8 : (g == 1) ? 6 : 7;
        float s = 0.f;
        for (int j = 0; j < n; ++j) s += probs[off + j] * w[o * n + j];
        out[2 * Bn + b * 6 + o * 3 + g] = s;
    }
}

// ---------------------------------------------------------------------------
extern "C" void kernel_launch(void* const* d_in, const int* in_sizes, int n_in,
                              void* d_out, int out_size)
{
    const float* bert    = (const float*)d_in[0];
    const int*   ids     = (const int*)  d_in[1];
    const int*   length  = (const int*)  d_in[2];
    const float* senti_w = (const float*)d_in[3];
    const float* senti_b = (const float*)d_in[4];
    const float* dense_w = (const float*)d_in[5];
    const float* dense_b = (const float*)d_in[6];
    const float* dec_w   = (const float*)d_in[7];
    const float* dec_b   = (const float*)d_in[8];
    const float* w0      = (const float*)d_in[9];
    const float* w1      = (const float*)d_in[10];
    const float* w2      = (const float*)d_in[11];
    float* out = (float*)d_out;

    kWA<<<NWB + Bn, 576>>>(dense_w, bert, ids, length, senti_w, senti_b, out);
    kB <<<dim3(Dn / 64, Bn / 64, KSPLIT), 128>>>();
    kCH<<<Bn, 768>>>(dense_b, dec_w, dec_b, w0, w1, w2, out);
}

// round 16
// speedup vs baseline: 1.3339x; 1.0295x over previous
#include <cuda_runtime.h>
#include <cuda_bf16.h>
#include <math.h>

#define Bn 256
#define Sn 128
#define Dn 768
#define K2 1536
#define MASK_ID 103
#define KSPLIT 16
#define KCH (K2 / KSPLIT)   // 96
#define NIT (KCH / 32)      // 3

// Scratch (__device__ globals; no allocs allowed)
__device__ __nv_bfloat16 g_featsH[Bn * K2];     // feats bf16 hi
__device__ __nv_bfloat16 g_featsL[Bn * K2];     // feats bf16 lo
__device__ __nv_bfloat16 g_WH[Dn * K2];         // dense_w bf16 hi
__device__ __nv_bfloat16 g_WL[Dn * K2];         // dense_w bf16 lo
__device__ float g_part[KSPLIT][Bn * Dn];       // split-K partials

static __device__ const int c_ids[21] = {
    2307, 2204, 3835, 2157, 6581, 2986, 5151, 3893,
    7929, 24791, 8699, 4257, 16021, 6623,
    6659, 2919, 11771, 3532, 11325, 4997, 13135
};

__device__ __forceinline__ void split_store(
    __nv_bfloat16* ph, __nv_bfloat16* pl, float v)
{
    const __nv_bfloat16 h = __float2bfloat16(v);
    *ph = h;
    *pl = __float2bfloat16(v - __bfloat162float(h));
}

// ---------------------------------------------------------------------------
// kW: split dense_w into bf16 hi/lo (576 thr, all used)
// ---------------------------------------------------------------------------
__global__ __launch_bounds__(576) void kW(const float* __restrict__ Wd)
{
    const int i = (blockIdx.x * 576 + threadIdx.x) * 4;
    const float4 v = *(const float4*)&Wd[i];
    __nv_bfloat16 h[4], l[4];
    h[0] = __float2bfloat16(v.x); l[0] = __float2bfloat16(v.x - __bfloat162float(h[0]));
    h[1] = __float2bfloat16(v.y); l[1] = __float2bfloat16(v.y - __bfloat162float(h[1]));
    h[2] = __float2bfloat16(v.z); l[2] = __float2bfloat16(v.z - __bfloat162float(h[2]));
    h[3] = __float2bfloat16(v.w); l[3] = __float2bfloat16(v.w - __bfloat162float(h[3]));
    *(uint2*)&g_WH[i] = *(uint2*)h;
    *(uint2*)&g_WL[i] = *(uint2*)l;
}

// ---------------------------------------------------------------------------
// kA: SINGLE-PASS attention via online softmax (all fp32, deterministic).
// One block per batch, 576 thr = 18 warps. Each warp streams rows s = w+18k,
// keeping the row in registers; maintains running (m, sum, acc[768]) with
// rescaling. Per-warp partials in dynamic smem (18*768 f32 = 55KB), combined
// in fixed order at the end.
// ---------------------------------------------------------------------------
#define SM_POOL_F (18 * Dn)            // floats of dynamic smem
#define SM_TOTAL  (SM_POOL_F * 4)      // 55296 bytes

extern "C" __global__ __launch_bounds__(576) void kA(
    const float* __restrict__ bert,
    const int*   __restrict__ ids,
    const int*   __restrict__ length,
    const float* __restrict__ senti_w,
    const float* __restrict__ senti_b,
    float*       __restrict__ out)
{
    extern __shared__ float pool[];    // [18][Dn]
    __shared__ float ml[Dn];
    __shared__ float red_m[18];
    __shared__ float red_s[18];
    __shared__ int   mp_s;

    const int b = blockIdx.x;
    const int t = threadIdx.x;
    const int warp = t >> 5, lane = t & 31;
    const int len = length[b];

    if (t < Sn && ids[b * Sn + t] == MASK_ID) mp_s = t;
    __syncthreads();
    const int mp = mp_s;
    const float* Xb = bert + (size_t)b * Sn * Dn;

    // ml -> smem + feats[768..1536) split-store
    for (int d = t; d < Dn; d += 576) {
        const float v = Xb[(size_t)mp * Dn + d];
        ml[d] = v;
        split_store(&g_featsH[(size_t)b * K2 + Dn + d],
                    &g_featsL[(size_t)b * K2 + Dn + d], v);
    }
    __syncthreads();

    // category head (pooler = row 0), warps 16/17 (also do score rows below)
    if (warp >= 16) {
        const int c = warp - 16;
        float s = 0.f;
        for (int d = lane * 4; d < Dn; d += 128) {
            const float4 x = *(const float4*)&Xb[d];
            const float4 w = *(const float4*)&senti_w[c * Dn + d];
            s += x.x * w.x + x.y * w.y + x.z * w.z + x.w * w.w;
        }
        #pragma unroll
        for (int o = 16; o > 0; o >>= 1) s += __shfl_xor_sync(0xffffffffu, s, o);
        if (lane == 0) out[b * 2 + c] = s + senti_b[c];
    }

    // ---- single pass: score + online-softmax accumulate ----
    float4 acc[6] = {};
    float m = -INFINITY, sum = 0.f;

    for (int s = warp; s < len; s += 18) {
        const float* row = Xb + (size_t)(s + 3) * Dn;
        float4 X[6];
        #pragma unroll
        for (int j = 0; j < 6; ++j)
            X[j] = *(const float4*)&row[j * 128 + lane * 4];

        float sc = 0.f;
        #pragma unroll
        for (int j = 0; j < 6; ++j) {
            const float4 mlv = *(const float4*)&ml[j * 128 + lane * 4];
            sc += X[j].x * mlv.x + X[j].y * mlv.y + X[j].z * mlv.z + X[j].w * mlv.w;
        }
        #pragma unroll
        for (int o = 16; o > 0; o >>= 1) sc += __shfl_xor_sync(0xffffffffu, sc, o);

        const float mn   = fmaxf(m, sc);
        const float corr = __expf(m - mn);    // m=-INF first iter -> 0
        const float e    = __expf(sc - mn);
        sum = sum * corr + e;
        #pragma unroll
        for (int j = 0; j < 6; ++j) {
            acc[j].x = acc[j].x * corr + e * X[j].x;
            acc[j].y = acc[j].y * corr + e * X[j].y;
            acc[j].z = acc[j].z * corr + e * X[j].z;
            acc[j].w = acc[j].w * corr + e * X[j].w;
        }
        m = mn;
    }

    #pragma unroll
    for (int j = 0; j < 6; ++j)
        *(float4*)&pool[warp * Dn + j * 128 + lane * 4] = acc[j];
    if (lane == 0) { red_m[warp] = m; red_s[warp] = sum; }
    __syncthreads();

    // ---- deterministic combine (192 threads, 4 dims each) ----
    if (t < 192) {
        float M = red_m[0];
        #pragma unroll
        for (int i = 1; i < 18; ++i) M = fmaxf(M, red_m[i]);
        float f[18];
        float total = 0.f;
        #pragma unroll
        for (int i = 0; i < 18; ++i) {
            f[i] = __expf(red_m[i] - M);
            total += red_s[i] * f[i];
        }
        const float inv = 1.f / total;

        const int d = t * 4;
        float4 sv = {0.f, 0.f, 0.f, 0.f};
        #pragma unroll
        for (int w = 0; w < 18; ++w) {
            const float4 p = *(const float4*)&pool[w * Dn + d];
            sv.x += f[w] * p.x; sv.y += f[w] * p.y;
            sv.z += f[w] * p.z; sv.w += f[w] * p.w;
        }
        float vv[4] = { sv.x * inv, sv.y * inv, sv.z * inv, sv.w * inv };
        __nv_bfloat16 h[4], l[4];
        #pragma unroll
        for (int i = 0; i < 4; ++i) {
            h[i] = __float2bfloat16(vv[i]);
            l[i] = __float2bfloat16(vv[i] - __bfloat162float(h[i]));
        }
        *(uint2*)&g_featsH[(size_t)b * K2 + d] = *(uint2*)h;
        *(uint2*)&g_featsL[(size_t)b * K2 + d] = *(uint2*)l;
    }
}

// ---------------------------------------------------------------------------
// kB: bf16 tensor-core GEMM (split-bf16 emulated fp32), cp.async 2-stage,
// Block 64(M) x 64(N), BK=32, 128 thr = 4 warps, KSPLIT=16.
// ---------------------------------------------------------------------------
#define LDK 40   // 80B rows, conflict-free ldmatrix

__device__ __forceinline__ void mma_bf16(
    float* c, const unsigned* a, const unsigned* b)
{
    asm volatile(
        "mma.sync.aligned.m16n8k16.row.col.f32.bf16.bf16.f32 "
        "{%0,%1,%2,%3}, {%4,%5,%6,%7}, {%8,%9}, {%0,%1,%2,%3};"
        : "+f"(c[0]), "+f"(c[1]), "+f"(c[2]), "+f"(c[3])
        : "r"(a[0]), "r"(a[1]), "r"(a[2]), "r"(a[3]), "r"(b[0]), "r"(b[1]));
}

__device__ __forceinline__ void ldsm4(unsigned* r, unsigned addr)
{
    asm volatile("ldmatrix.sync.aligned.m8n8.x4.shared.b16 {%0,%1,%2,%3}, [%4];"
                 : "=r"(r[0]), "=r"(r[1]), "=r"(r[2]), "=r"(r[3]) : "r"(addr));
}

__device__ __forceinline__ void cp16(void* dst, const void* src)
{
    const unsigned d = (unsigned)__cvta_generic_to_shared(dst);
    asm volatile("cp.async.ca.shared.global [%0], [%1], 16;" :: "r"(d), "l"(src));
}

__global__ __launch_bounds__(128) void kB()
{
    __shared__ __nv_bfloat16 smem[2][4][64 * LDK];

    const int t = threadIdx.x;
    const int warp = t >> 5, lane = t & 31;
    const int bn = blockIdx.x * 64;
    const int bm = blockIdx.y * 64;
    const int kbase = blockIdx.z * KCH;
    const int wm = warp & 1, wn = warp >> 1;

    float acc[2][4][4] = {};

    const int row = t >> 2;
    const int cq  = (t & 3) * 8;

    #define ISSUE(it, stg) do {                                                   \
        const int kg = kbase + (it) * 32;                                          \
        _Pragma("unroll")                                                          \
        for (int i = 0; i < 2; ++i) {                                              \
            const int r = row + i * 32;                                            \
            cp16(&smem[stg][0][r * LDK + cq], &g_featsH[(size_t)(bm + r) * K2 + kg + cq]); \
            cp16(&smem[stg][1][r * LDK + cq], &g_featsL[(size_t)(bm + r) * K2 + kg + cq]); \
            cp16(&smem[stg][2][r * LDK + cq], &g_WH[(size_t)(bn + r) * K2 + kg + cq]);     \
            cp16(&smem[stg][3][r * LDK + cq], &g_WL[(size_t)(bn + r) * K2 + kg + cq]);     \
        }                                                                          \
        asm volatile("cp.async.commit_group;");                                    \
    } while (0)

    ISSUE(0, 0);

    for (int it = 0; it < NIT; ++it) {
        const int stg = it & 1;
        if (it + 1 < NIT) {
            ISSUE(it + 1, stg ^ 1);
            asm volatile("cp.async.wait_group 1;");
        } else {
            asm volatile("cp.async.wait_group 0;");
        }
        __syncthreads();

        const unsigned ah_b = (unsigned)__cvta_generic_to_shared(smem[stg][0]);
        const unsigned al_b = (unsigned)__cvta_generic_to_shared(smem[stg][1]);
        const unsigned bh_b = (unsigned)__cvta_generic_to_shared(smem[stg][2]);
        const unsigned bl_b = (unsigned)__cvta_generic_to_shared(smem[stg][3]);

        #pragma unroll
        for (int kk = 0; kk < 32; kk += 16) {
            unsigned Ah[2][4], Al[2][4];
            #pragma unroll
            for (int tm = 0; tm < 2; ++tm) {
                const unsigned off =
                    (unsigned)(((wm * 32 + tm * 16 + (lane & 15)) * LDK
                               + kk + (lane >> 4) * 8) * 2);
                ldsm4(Ah[tm], ah_b + off);
                ldsm4(Al[tm], al_b + off);
            }
            unsigned Bh[4][2], Bl[4][2];
            #pragma unroll
            for (int bj = 0; bj < 2; ++bj) {
                const int quad = lane >> 3, l8 = lane & 7;
                const int n = wn * 32 + bj * 16 + (quad >> 1) * 8 + l8;
                const int k = kk + (quad & 1) * 8;
                const unsigned off = (unsigned)((n * LDK + k) * 2);
                unsigned r4[4];
                ldsm4(r4, bh_b + off);
                Bh[bj * 2][0] = r4[0]; Bh[bj * 2][1] = r4[1];
                Bh[bj * 2 + 1][0] = r4[2]; Bh[bj * 2 + 1][1] = r4[3];
                ldsm4(r4, bl_b + off);
                Bl[bj * 2][0] = r4[0]; Bl[bj * 2][1] = r4[1];
                Bl[bj * 2 + 1][0] = r4[2]; Bl[bj * 2 + 1][1] = r4[3];
            }
            #pragma unroll
            for (int tm = 0; tm < 2; ++tm)
                #pragma unroll
                for (int tn = 0; tn < 4; ++tn) {
                    mma_bf16(acc[tm][tn], Ah[tm], Bh[tn]);
                    mma_bf16(acc[tm][tn], Ah[tm], Bl[tn]);
                    mma_bf16(acc[tm][tn], Al[tm], Bh[tn]);
                }
        }
        __syncthreads();
    }

    float* P = g_part[blockIdx.z];
    const int r0 = bm + wm * 32 + (lane >> 2);
    const int c0 = bn + wn * 32 + (lane & 3) * 2;
    #pragma unroll
    for (int tm = 0; tm < 2; ++tm)
        #pragma unroll
        for (int tn = 0; tn < 4; ++tn) {
            const int r = r0 + tm * 16;
            const int c = c0 + tn * 8;
            *(float2*)&P[(size_t)r * Dn + c]       = make_float2(acc[tm][tn][0], acc[tm][tn][1]);
            *(float2*)&P[(size_t)(r + 8) * Dn + c] = make_float2(acc[tm][tn][2], acc[tm][tn][3]);
        }
}

// ---------------------------------------------------------------------------
// kCH: fused split-K reduce + bias + tanh + decoder + mixes.
// 256 blocks x 768 thr; thread t reduces element d=t (16 coalesced loads).
// ---------------------------------------------------------------------------
__global__ __launch_bounds__(768) void kCH(
    const float* __restrict__ dense_b,
    const float* __restrict__ dec_w,
    const float* __restrict__ dec_b,
    const float* __restrict__ w0,
    const float* __restrict__ w1,
    const float* __restrict__ w2,
    float*       __restrict__ out)
{
    const int b = blockIdx.x;
    const int t = threadIdx.x;
    const int warp = t >> 5, lane = t & 31;

    __shared__ float hs[Dn];
    __shared__ float probs[21];

    {
        const size_t gi = (size_t)b * Dn + t;
        float p[KSPLIT];
        #pragma unroll
        for (int k = 0; k < KSPLIT; ++k) p[k] = g_part[k][gi];
        float s = dense_b[t];
        #pragma unroll
        for (int k = 0; k < KSPLIT; ++k) s += p[k];
        hs[t] = tanhf(s);
    }
    __syncthreads();

    if (warp < 21) {
        const int v = c_ids[warp];
        const float* rw = dec_w + (size_t)v * Dn;
        float s = 0.f;
        #pragma unroll
        for (int j = 0; j < 6; ++j) {
            const int d = j * 128 + lane * 4;
            const float4 h4 = *(const float4*)&hs[d];
            const float4 r4 = *(const float4*)&rw[d];
            s += h4.x * r4.x + h4.y * r4.y + h4.z * r4.z + h4.w * r4.w;
        }
        #pragma unroll
        for (int o = 16; o > 0; o >>= 1) s += __shfl_xor_sync(0xffffffffu, s, o);
        if (lane == 0) probs[warp] = tanhf(s + dec_b[v]);
    }
    __syncthreads();

    if (t < 6) {
        const int o = t / 3, g = t % 3;
        const float* w = (g == 0) ? w0 : (g == 1) ? w1 : w2;
        const int off = (g == 0) ? 0 : (g == 1) ? 8 : 14;
        const int n   = (g == 0) ? 8 : (g == 1) ? 6 : 7;
        float s = 0.f;
        for (int j = 0; j < n; ++j) s += probs[off + j] * w[o * n + j];
        out[2 * Bn + b * 6 + o * 3 + g] = s;
    }
}

// ---------------------------------------------------------------------------
extern "C" void kernel_launch(void* const* d_in, const int* in_sizes, int n_in,
                              void* d_out, int out_size)
{
    const float* bert    = (const float*)d_in[0];
    const int*   ids     = (const int*)  d_in[1];
    const int*   length  = (const int*)  d_in[2];
    const float* senti_w = (const float*)d_in[3];
    const float* senti_b = (const float*)d_in[4];
    const float* dense_w = (const float*)d_in[5];
    const float* dense_b = (const float*)d_in[6];
    const float* dec_w   = (const float*)d_in[7];
    const float* dec_b   = (const float*)d_in[8];
    const float* w0      = (const float*)d_in[9];
    const float* w1      = (const float*)d_in[10];
    const float* w2      = (const float*)d_in[11];
    float* out = (float*)d_out;

    cudaFuncSetAttribute(kA, cudaFuncAttributeMaxDynamicSharedMemorySize, SM_TOTAL);

    kW <<<(Dn * K2) / (576 * 4), 576>>>(dense_w);
    kA <<<Bn, 576, SM_TOTAL>>>(bert, ids, length, senti_w, senti_b, out);
    kB <<<dim3(Dn / 64, Bn / 64, KSPLIT), 128>>>();
    kCH<<<Bn, 768>>>(dense_b, dec_w, dec_b, w0, w1, w2, out);
}

// round 17
// speedup vs baseline: 1.3533x; 1.0145x over previous
#include <cuda_runtime.h>
#include <cuda_bf16.h>
#include <math.h>

#define Bn 256
#define Sn 128
#define Dn 768
#define K2 1536
#define MASK_ID 103
#define KSPLIT 16
#define KCH (K2 / KSPLIT)   // 96
#define NIT (KCH / 32)      // 3
#define NWB ((Dn * K2) / (576 * 4))   // 512 blocks for W-split

// Scratch (__device__ globals; no allocs allowed)
__device__ __nv_bfloat16 g_featsH[Bn * K2];     // feats bf16 hi
__device__ __nv_bfloat16 g_featsL[Bn * K2];     // feats bf16 lo
__device__ __nv_bfloat16 g_WH[Dn * K2];         // dense_w bf16 hi
__device__ __nv_bfloat16 g_WL[Dn * K2];         // dense_w bf16 lo
__device__ float g_part[KSPLIT][Bn * Dn];       // split-K partials

static __device__ const int c_ids[21] = {
    2307, 2204, 3835, 2157, 6581, 2986, 5151, 3893,
    7929, 24791, 8699, 4257, 16021, 6623,
    6659, 2919, 11771, 3532, 11325, 4997, 13135
};

__device__ __forceinline__ void split_store(
    __nv_bfloat16* ph, __nv_bfloat16* pl, float v)
{
    const __nv_bfloat16 h = __float2bfloat16(v);
    *ph = h;
    *pl = __float2bfloat16(v - __bfloat162float(h));
}

// ---------------------------------------------------------------------------
// kWA: fused pre-work.
//  blocks [0, NWB): dense_w bf16 hi/lo split (576*4 floats per block)
//  blocks [NWB, NWB+Bn): single-pass online-softmax attention (576 thr)
// Dynamic smem: pool[18][Dn] f32 (55KB) for attention blocks.
// ---------------------------------------------------------------------------
#define SM_POOL_F (18 * Dn)
#define SM_TOTAL  (SM_POOL_F * 4)      // 55296 bytes

extern "C" __global__ __launch_bounds__(576) void kWA(
    const float* __restrict__ Wd,
    const float* __restrict__ bert,
    const int*   __restrict__ ids,
    const int*   __restrict__ length,
    const float* __restrict__ senti_w,
    const float* __restrict__ senti_b,
    float*       __restrict__ out)
{
    const int t = threadIdx.x;

    if (blockIdx.x < NWB) {
        const int i = (blockIdx.x * 576 + t) * 4;
        const float4 v = *(const float4*)&Wd[i];
        __nv_bfloat16 h[4], l[4];
        h[0] = __float2bfloat16(v.x); l[0] = __float2bfloat16(v.x - __bfloat162float(h[0]));
        h[1] = __float2bfloat16(v.y); l[1] = __float2bfloat16(v.y - __bfloat162float(h[1]));
        h[2] = __float2bfloat16(v.z); l[2] = __float2bfloat16(v.z - __bfloat162float(h[2]));
        h[3] = __float2bfloat16(v.w); l[3] = __float2bfloat16(v.w - __bfloat162float(h[3]));
        *(uint2*)&g_WH[i] = *(uint2*)h;
        *(uint2*)&g_WL[i] = *(uint2*)l;
        return;
    }

    extern __shared__ float pool[];    // [18][Dn]
    __shared__ float ml[Dn];
    __shared__ float red_m[18];
    __shared__ float red_s[18];
    __shared__ int   mp_s;

    const int b = blockIdx.x - NWB;
    const int warp = t >> 5, lane = t & 31;
    const int len = length[b];

    if (t < Sn && ids[b * Sn + t] == MASK_ID) mp_s = t;
    __syncthreads();
    const int mp = mp_s;
    const float* Xb = bert + (size_t)b * Sn * Dn;

    // ml -> smem + feats[768..1536) split-store
    for (int d = t; d < Dn; d += 576) {
        const float v = Xb[(size_t)mp * Dn + d];
        ml[d] = v;
        split_store(&g_featsH[(size_t)b * K2 + Dn + d],
                    &g_featsL[(size_t)b * K2 + Dn + d], v);
    }
    __syncthreads();

    // category head (pooler = row 0), warps 16/17
    if (warp >= 16) {
        const int c = warp - 16;
        float s = 0.f;
        for (int d = lane * 4; d < Dn; d += 128) {
            const float4 x = *(const float4*)&Xb[d];
            const float4 w = *(const float4*)&senti_w[c * Dn + d];
            s += x.x * w.x + x.y * w.y + x.z * w.z + x.w * w.w;
        }
        #pragma unroll
        for (int o = 16; o > 0; o >>= 1) s += __shfl_xor_sync(0xffffffffu, s, o);
        if (lane == 0) out[b * 2 + c] = s + senti_b[c];
    }

    // ---- single pass: score + online-softmax accumulate ----
    float4 acc[6] = {};
    float m = -INFINITY, sum = 0.f;

    for (int s = warp; s < len; s += 18) {
        const float* row = Xb + (size_t)(s + 3) * Dn;
        float4 X[6];
        #pragma unroll
        for (int j = 0; j < 6; ++j)
            X[j] = *(const float4*)&row[j * 128 + lane * 4];

        float sc = 0.f;
        #pragma unroll
        for (int j = 0; j < 6; ++j) {
            const float4 mlv = *(const float4*)&ml[j * 128 + lane * 4];
            sc += X[j].x * mlv.x + X[j].y * mlv.y + X[j].z * mlv.z + X[j].w * mlv.w;
        }
        #pragma unroll
        for (int o = 16; o > 0; o >>= 1) sc += __shfl_xor_sync(0xffffffffu, sc, o);

        const float mn   = fmaxf(m, sc);
        const float corr = __expf(m - mn);
        const float e    = __expf(sc - mn);
        sum = sum * corr + e;
        #pragma unroll
        for (int j = 0; j < 6; ++j) {
            acc[j].x = acc[j].x * corr + e * X[j].x;
            acc[j].y = acc[j].y * corr + e * X[j].y;
            acc[j].z = acc[j].z * corr + e * X[j].z;
            acc[j].w = acc[j].w * corr + e * X[j].w;
        }
        m = mn;
    }

    #pragma unroll
    for (int j = 0; j < 6; ++j)
        *(float4*)&pool[warp * Dn + j * 128 + lane * 4] = acc[j];
    if (lane == 0) { red_m[warp] = m; red_s[warp] = sum; }
    __syncthreads();

    // ---- deterministic combine (192 threads, 4 dims each) ----
    if (t < 192) {
        float M = red_m[0];
        #pragma unroll
        for (int i = 1; i < 18; ++i) M = fmaxf(M, red_m[i]);
        float f[18];
        float total = 0.f;
        #pragma unroll
        for (int i = 0; i < 18; ++i) {
            f[i] = __expf(red_m[i] - M);
            total += red_s[i] * f[i];
        }
        const float inv = 1.f / total;

        const int d = t * 4;
        float4 sv = {0.f, 0.f, 0.f, 0.f};
        #pragma unroll
        for (int w = 0; w < 18; ++w) {
            const float4 p = *(const float4*)&pool[w * Dn + d];
            sv.x += f[w] * p.x; sv.y += f[w] * p.y;
            sv.z += f[w] * p.z; sv.w += f[w] * p.w;
        }
        float vv[4] = { sv.x * inv, sv.y * inv, sv.z * inv, sv.w * inv };
        __nv_bfloat16 h[4], l[4];
        #pragma unroll
        for (int i = 0; i < 4; ++i) {
            h[i] = __float2bfloat16(vv[i]);
            l[i] = __float2bfloat16(vv[i] - __bfloat162float(h[i]));
        }
        *(uint2*)&g_featsH[(size_t)b * K2 + d] = *(uint2*)h;
        *(uint2*)&g_featsL[(size_t)b * K2 + d] = *(uint2*)l;
    }
}

// ---------------------------------------------------------------------------
// kB: bf16 tensor-core GEMM (split-bf16 emulated fp32), cp.async 2-stage,
// Block 64(M) x 64(N), BK=32, 128 thr = 4 warps, KSPLIT=16.
// ---------------------------------------------------------------------------
#define LDK 40   // 80B rows, conflict-free ldmatrix

__device__ __forceinline__ void mma_bf16(
    float* c, const unsigned* a, const unsigned* b)
{
    asm volatile(
        "mma.sync.aligned.m16n8k16.row.col.f32.bf16.bf16.f32 "
        "{%0,%1,%2,%3}, {%4,%5,%6,%7}, {%8,%9}, {%0,%1,%2,%3};"
        : "+f"(c[0]), "+f"(c[1]), "+f"(c[2]), "+f"(c[3])
        : "r"(a[0]), "r"(a[1]), "r"(a[2]), "r"(a[3]), "r"(b[0]), "r"(b[1]));
}

__device__ __forceinline__ void ldsm4(unsigned* r, unsigned addr)
{
    asm volatile("ldmatrix.sync.aligned.m8n8.x4.shared.b16 {%0,%1,%2,%3}, [%4];"
                 : "=r"(r[0]), "=r"(r[1]), "=r"(r[2]), "=r"(r[3]) : "r"(addr));
}

__device__ __forceinline__ void cp16(void* dst, const void* src)
{
    const unsigned d = (unsigned)__cvta_generic_to_shared(dst);
    asm volatile("cp.async.ca.shared.global [%0], [%1], 16;" :: "r"(d), "l"(src));
}

__global__ __launch_bounds__(128) void kB()
{
    __shared__ __nv_bfloat16 smem[2][4][64 * LDK];

    const int t = threadIdx.x;
    const int warp = t >> 5, lane = t & 31;
    const int bn = blockIdx.x * 64;
    const int bm = blockIdx.y * 64;
    const int kbase = blockIdx.z * KCH;
    const int wm = warp & 1, wn = warp >> 1;

    float acc[2][4][4] = {};

    const int row = t >> 2;
    const int cq  = (t & 3) * 8;

    #define ISSUE(it, stg) do {                                                   \
        const int kg = kbase + (it) * 32;                                          \
        _Pragma("unroll")                                                          \
        for (int i = 0; i < 2; ++i) {                                              \
            const int r = row + i * 32;                                            \
            cp16(&smem[stg][0][r * LDK + cq], &g_featsH[(size_t)(bm + r) * K2 + kg + cq]); \
            cp16(&smem[stg][1][r * LDK + cq], &g_featsL[(size_t)(bm + r) * K2 + kg + cq]); \
            cp16(&smem[stg][2][r * LDK + cq], &g_WH[(size_t)(bn + r) * K2 + kg + cq]);     \
            cp16(&smem[stg][3][r * LDK + cq], &g_WL[(size_t)(bn + r) * K2 + kg + cq]);     \
        }                                                                          \
        asm volatile("cp.async.commit_group;");                                    \
    } while (0)

    ISSUE(0, 0);

    for (int it = 0; it < NIT; ++it) {
        const int stg = it & 1;
        if (it + 1 < NIT) {
            ISSUE(it + 1, stg ^ 1);
            asm volatile("cp.async.wait_group 1;");
        } else {
            asm volatile("cp.async.wait_group 0;");
        }
        __syncthreads();

        const unsigned ah_b = (unsigned)__cvta_generic_to_shared(smem[stg][0]);
        const unsigned al_b = (unsigned)__cvta_generic_to_shared(smem[stg][1]);
        const unsigned bh_b = (unsigned)__cvta_generic_to_shared(smem[stg][2]);
        const unsigned bl_b = (unsigned)__cvta_generic_to_shared(smem[stg][3]);

        #pragma unroll
        for (int kk = 0; kk < 32; kk += 16) {
            unsigned Ah[2][4], Al[2][4];
            #pragma unroll
            for (int tm = 0; tm < 2; ++tm) {
                const unsigned off =
                    (unsigned)(((wm * 32 + tm * 16 + (lane & 15)) * LDK
                               + kk + (lane >> 4) * 8) * 2);
                ldsm4(Ah[tm], ah_b + off);
                ldsm4(Al[tm], al_b + off);
            }
            unsigned Bh[4][2], Bl[4][2];
            #pragma unroll
            for (int bj = 0; bj < 2; ++bj) {
                const int quad = lane >> 3, l8 = lane & 7;
                const int n = wn * 32 + bj * 16 + (quad >> 1) * 8 + l8;
                const int k = kk + (quad & 1) * 8;
                const unsigned off = (unsigned)((n * LDK + k) * 2);
                unsigned r4[4];
                ldsm4(r4, bh_b + off);
                Bh[bj * 2][0] = r4[0]; Bh[bj * 2][1] = r4[1];
                Bh[bj * 2 + 1][0] = r4[2]; Bh[bj * 2 + 1][1] = r4[3];
                ldsm4(r4, bl_b + off);
                Bl[bj * 2][0] = r4[0]; Bl[bj * 2][1] = r4[1];
                Bl[bj * 2 + 1][0] = r4[2]; Bl[bj * 2 + 1][1] = r4[3];
            }
            #pragma unroll
            for (int tm = 0; tm < 2; ++tm)
                #pragma unroll
                for (int tn = 0; tn < 4; ++tn) {
                    mma_bf16(acc[tm][tn], Ah[tm], Bh[tn]);
                    mma_bf16(acc[tm][tn], Ah[tm], Bl[tn]);
                    mma_bf16(acc[tm][tn], Al[tm], Bh[tn]);
                }
        }
        __syncthreads();
    }

    float* P = g_part[blockIdx.z];
    const int r0 = bm + wm * 32 + (lane >> 2);
    const int c0 = bn + wn * 32 + (lane & 3) * 2;
    #pragma unroll
    for (int tm = 0; tm < 2; ++tm)
        #pragma unroll
        for (int tn = 0; tn < 4; ++tn) {
            const int r = r0 + tm * 16;
            const int c = c0 + tn * 8;
            *(float2*)&P[(size_t)r * Dn + c]       = make_float2(acc[tm][tn][0], acc[tm][tn][1]);
            *(float2*)&P[(size_t)(r + 8) * Dn + c] = make_float2(acc[tm][tn][2], acc[tm][tn][3]);
        }
}

// ---------------------------------------------------------------------------
// kCH: fused split-K reduce + bias + tanh + decoder + mixes.
// 256 blocks x 768 thr, __launch_bounds__(768, 2) => <=42 regs, 2 blocks/SM,
// 48 warps/SM, single wave. Reduce in two 8-deep load batches.
// ---------------------------------------------------------------------------
__global__ __launch_bounds__(768, 2) void kCH(
    const float* __restrict__ dense_b,
    const float* __restrict__ dec_w,
    const float* __restrict__ dec_b,
    const float* __restrict__ w0,
    const float* __restrict__ w1,
    const float* __restrict__ w2,
    float*       __restrict__ out)
{
    const int b = blockIdx.x;
    const int t = threadIdx.x;
    const int warp = t >> 5, lane = t & 31;

    __shared__ float hs[Dn];
    __shared__ float probs[21];

    {
        const size_t gi = (size_t)b * Dn + t;
        float p0[8];
        #pragma unroll
        for (int k = 0; k < 8; ++k) p0[k] = g_part[k][gi];
        float s = dense_b[t];
        #pragma unroll
        for (int k = 0; k < 8; ++k) s += p0[k];
        float p1[8];
        #pragma unroll
        for (int k = 0; k < 8; ++k) p1[k] = g_part[8 + k][gi];
        #pragma unroll
        for (int k = 0; k < 8; ++k) s += p1[k];
        hs[t] = tanhf(s);
    }
    __syncthreads();

    if (warp < 21) {
        const int v = c_ids[warp];
        const float* rw = dec_w + (size_t)v * Dn;
        float s = 0.f;
        #pragma unroll
        for (int j = 0; j < 6; ++j) {
            const int d = j * 128 + lane * 4;
            const float4 h4 = *(const float4*)&hs[d];
            const float4 r4 = *(const float4*)&rw[d];
            s += h4.x * r4.x + h4.y * r4.y + h4.z * r4.z + h4.w * r4.w;
        }
        #pragma unroll
        for (int o = 16; o > 0; o >>= 1) s += __shfl_xor_sync(0xffffffffu, s, o);
        if (lane == 0) probs[warp] = tanhf(s + dec_b[v]);
    }
    __syncthreads();

    if (t < 6) {
        const int o = t / 3, g = t % 3;
        const float* w = (g == 0) ? w0 : (g == 1) ? w1 : w2;
        const int off = (g == 0) ? 0 : (g == 1) ? 8 : 14;
        const int n   = (g == 0) ? 8 : (g == 1) ? 6 : 7;
        float s = 0.f;
        for (int j = 0; j < n; ++j) s += probs[off + j] * w[o * n + j];
        out[2 * Bn + b * 6 + o * 3 + g] = s;
    }
}

// ---------------------------------------------------------------------------
extern "C" void kernel_launch(void* const* d_in, const int* in_sizes, int n_in,
                              void* d_out, int out_size)
{
    const float* bert    = (const float*)d_in[0];
    const int*   ids     = (const int*)  d_in[1];
    const int*   length  = (const int*)  d_in[2];
    const float* senti_w = (const float*)d_in[3];
    const float* senti_b = (const float*)d_in[4];
    const float* dense_w = (const float*)d_in[5];
    const float* dense_b = (const float*)d_in[6];
    const float* dec_w   = (const float*)d_in[7];
    const float* dec_b   = (const float*)d_in[8];
    const float* w0      = (const float*)d_in[9];
    const float* w1      = (const float*)d_in[10];
    const float* w2      = (const float*)d_in[11];
    float* out = (float*)d_out;

    cudaFuncSetAttribute(kWA, cudaFuncAttributeMaxDynamicSharedMemorySize, SM_TOTAL);

    kWA<<<NWB + Bn, 576, SM_TOTAL>>>(dense_w, bert, ids, length, senti_w, senti_b, out);
    kB <<<dim3(Dn / 64, Bn / 64, KSPLIT), 128>>>();
    kCH<<<Bn, 768>>>(dense_b, dec_w, dec_b, w0, w1, w2, out);
}